// round 6
// baseline (speedup 1.0000x reference)
#include <cuda_runtime.h>
#include <cuda_bf16.h>
#include <cstdint>

// Problem constants (fixed shapes)
#define V_N 50000
#define E_N 800000
#define TM  64     // node-kernel rows per tile
#define NT  256

// Scratch (static device arrays — no runtime allocation)
__device__ float g_agg[(size_t)V_N * 128];  // scatter-add accumulator (25.6 MB)

// ============================================================================
// Warp-level MMA helpers (base PTX: ldmatrix sm_75+, mma.sync bf16 sm_80+)
// ============================================================================
__device__ __forceinline__ uint32_t smem_u32(const void* p) {
    uint32_t a;
    asm("{ .reg .u64 t; cvta.to.shared.u64 t, %1; cvt.u32.u64 %0, t; }"
        : "=r"(a) : "l"(p));
    return a;
}

__device__ __forceinline__ void ldsm_x4(uint32_t* r, uint32_t addr) {
    asm volatile("ldmatrix.sync.aligned.m8n8.x4.shared.b16 {%0,%1,%2,%3}, [%4];"
                 : "=r"(r[0]), "=r"(r[1]), "=r"(r[2]), "=r"(r[3]) : "r"(addr));
}
__device__ __forceinline__ void ldsm_x4_t(uint32_t* r, uint32_t addr) {
    asm volatile("ldmatrix.sync.aligned.m8n8.x4.trans.shared.b16 {%0,%1,%2,%3}, [%4];"
                 : "=r"(r[0]), "=r"(r[1]), "=r"(r[2]), "=r"(r[3]) : "r"(addr));
}
__device__ __forceinline__ void mma_bf16(float* d, const uint32_t* a, const uint32_t* b) {
    asm volatile(
        "mma.sync.aligned.m16n8k16.row.col.f32.bf16.bf16.f32 "
        "{%0,%1,%2,%3}, {%4,%5,%6,%7}, {%8,%9}, {%0,%1,%2,%3};"
        : "+f"(d[0]), "+f"(d[1]), "+f"(d[2]), "+f"(d[3])
        : "r"(a[0]), "r"(a[1]), "r"(a[2]), "r"(a[3]), "r"(b[0]), "r"(b[1]));
}
__device__ __forceinline__ uint32_t pack2(float a, float b) {
    __nv_bfloat162 p = __floats2bfloat162_rn(a, b);
    return *(uint32_t*)&p;
}
__device__ __forceinline__ void red_add_v4(float* p, float a, float b, float c, float d) {
    asm volatile("red.global.add.v4.f32 [%0], {%1, %2, %3, %4};"
                 :: "l"(p), "f"(a), "f"(b), "f"(c), "f"(d) : "memory");
}

// ---------------------------------------------------------------------------
// SMEM layout for the edge kernel (bytes). Weight rows padded to 272B,
// activation rows to 528B -> conflict-free ldmatrix (68/132 words mod 32 = 4).
// ---------------------------------------------------------------------------
#define SM_IDX 0        // 128 ints (src[64], dst[64])
#define SM_BB1 512      // 128 floats
#define SM_BB2 1024
#define SM_BB3 1536
#define SM_W1  2048     // 256 rows x 272B = 69632
#define SM_W2  71680    // 128 x 272B = 34816
#define SM_W3  106496   // 128 x 272B = 34816
#define SM_A2  141312   // 64 x 272B  = 17408 (bf16 activations L2 input)
#define SM_XS  158720   // 64 x 528B  = 33792 (X input / A3 / fp32 staging)
#define SM_EDGE_TOTAL 192512

#define WPITCH 272
#define XPITCH 528

// Warp-tile GEMM: D(32x32) += A(32xK) @ W(KxN)^(col frag), A rows at
// wr*32, W cols at wc*32. A base pitch AP, weights pitch 272.
template <int NK, int AP>
__device__ __forceinline__ void gemm_tile(uint32_t abase, uint32_t wbase,
                                          int wr, int wc, int lane,
                                          float d[2][4][4]) {
    const int l15 = lane & 15;
    const int kh  = (lane >> 4) << 3;   // 0 or 8
#pragma unroll
    for (int mi = 0; mi < 2; mi++)
#pragma unroll
        for (int ni = 0; ni < 4; ni++)
#pragma unroll
            for (int x = 0; x < 4; x++) d[mi][ni][x] = 0.f;

#pragma unroll
    for (int ks = 0; ks < NK; ks++) {
        uint32_t a[2][4], b[4][2];
#pragma unroll
        for (int mi = 0; mi < 2; mi++) {
            uint32_t addr = abase + (uint32_t)((wr * 32 + mi * 16 + l15) * AP +
                                               (ks * 16 + kh) * 2);
            ldsm_x4(a[mi], addr);
        }
#pragma unroll
        for (int nj = 0; nj < 2; nj++) {
            uint32_t addr = wbase + (uint32_t)((ks * 16 + l15) * WPITCH +
                                               (wc * 32 + nj * 16 + kh) * 2);
            uint32_t t[4];
            ldsm_x4_t(t, addr);
            b[2 * nj][0] = t[0]; b[2 * nj][1] = t[1];
            b[2 * nj + 1][0] = t[2]; b[2 * nj + 1][1] = t[3];
        }
#pragma unroll
        for (int mi = 0; mi < 2; mi++)
#pragma unroll
            for (int ni = 0; ni < 4; ni++)
                mma_bf16(d[mi][ni], a[mi], b[ni]);
    }
}

// Epilogue: relu(d + bias) -> bf16 tile at dstbase (pitch P bytes)
template <int P>
__device__ __forceinline__ void epi_relu_bf16(char* dstbase, const float* bias,
                                              float d[2][4][4],
                                              int wr, int wc, int lane) {
    const int g = lane >> 2, q = lane & 3;
#pragma unroll
    for (int mi = 0; mi < 2; mi++) {
        const int rA = wr * 32 + mi * 16 + g;
#pragma unroll
        for (int ni = 0; ni < 4; ni++) {
            const int c = wc * 32 + ni * 8 + 2 * q;
            float2 bb = *(const float2*)&bias[c];
            float v0 = fmaxf(d[mi][ni][0] + bb.x, 0.f);
            float v1 = fmaxf(d[mi][ni][1] + bb.y, 0.f);
            float v2 = fmaxf(d[mi][ni][2] + bb.x, 0.f);
            float v3 = fmaxf(d[mi][ni][3] + bb.y, 0.f);
            *(uint32_t*)(dstbase + rA * P + c * 2)       = pack2(v0, v1);
            *(uint32_t*)(dstbase + (rA + 8) * P + c * 2) = pack2(v2, v3);
        }
    }
}

// ---------------------------------------------------------------------------
// Zero the aggregation buffer
// ---------------------------------------------------------------------------
__global__ void k_zero_agg() {
    const int n4 = V_N * 128 / 4;
    float4 z = make_float4(0.f, 0.f, 0.f, 0.f);
    for (int i = blockIdx.x * blockDim.x + threadIdx.x; i < n4;
         i += gridDim.x * blockDim.x)
        ((float4*)g_agg)[i] = z;
}

// ---------------------------------------------------------------------------
// Fused edge MLP (3 layers, bf16 mma.sync) + vectorized scatter-add.
// Tile = 64 edges x 128 outputs. 8 warps: grid 2(rows of 32) x 4(cols of 32).
// ---------------------------------------------------------------------------
__global__ __launch_bounds__(NT, 1) void k_edge(
    const float* __restrict__ h, const int* __restrict__ ei,
    const float* __restrict__ W1, const float* __restrict__ b1,
    const float* __restrict__ W2, const float* __restrict__ b2,
    const float* __restrict__ W3, const float* __restrict__ b3)
{
    extern __shared__ __align__(16) char sm[];
    int*   idxs = (int*)(sm + SM_IDX);
    float* b1s  = (float*)(sm + SM_BB1);
    float* b2s  = (float*)(sm + SM_BB2);
    float* b3s  = (float*)(sm + SM_BB3);
    const uint32_t sbase = smem_u32(sm);
    const uint32_t sW1 = sbase + SM_W1, sW2 = sbase + SM_W2, sW3 = sbase + SM_W3;
    const uint32_t sA2 = sbase + SM_A2, sXS = sbase + SM_XS;

    const int tid = threadIdx.x, wid = tid >> 5, lane = tid & 31;
    const int wr = wid & 1, wc = wid >> 1;

    // Stage weights as bf16 (row-major [k][n], padded pitch) + biases
    for (int i = tid; i < 256 * 128; i += NT) {
        int k = i >> 7, n = i & 127;
        *(__nv_bfloat16*)(sm + SM_W1 + k * WPITCH + n * 2) = __float2bfloat16(W1[i]);
    }
    for (int i = tid; i < 128 * 128; i += NT) {
        int k = i >> 7, n = i & 127;
        *(__nv_bfloat16*)(sm + SM_W2 + k * WPITCH + n * 2) = __float2bfloat16(W2[i]);
        *(__nv_bfloat16*)(sm + SM_W3 + k * WPITCH + n * 2) = __float2bfloat16(W3[i]);
    }
    if (tid < 128) { b1s[tid] = b1[tid]; b2s[tid] = b2[tid]; b3s[tid] = b3[tid]; }
    __syncthreads();

    const float4* h4 = (const float4*)h;
    float d[2][4][4];
    const int numTiles = E_N / 64;   // 12500

    for (int tile = blockIdx.x; tile < numTiles; tile += gridDim.x) {
        const int e0 = tile * 64;

        // ---- indices + gather [h[src] | h[dst]] -> Xs bf16 (64 x 256) ----
        if (tid < 64)       idxs[tid] = ei[e0 + tid];
        else if (tid < 128) idxs[tid] = ei[E_N + e0 + (tid - 64)];
        __syncthreads();
        for (int i = tid; i < 64 * 64; i += NT) {
            int r = i >> 6, j = i & 63;
            int node = (j < 32) ? idxs[r] : idxs[64 + r];
            float4 v = h4[(size_t)node * 32 + (j & 31)];
            uint2 u;
            u.x = pack2(v.x, v.y);
            u.y = pack2(v.z, v.w);
            *(uint2*)(sm + SM_XS + r * XPITCH + j * 8) = u;
        }
        __syncthreads();

        // ---- GEMM1 (K=256): A2 = relu(X @ W1 + b1) ----
        gemm_tile<16, XPITCH>(sXS, sW1, wr, wc, lane, d);
        epi_relu_bf16<WPITCH>(sm + SM_A2, b1s, d, wr, wc, lane);
        __syncthreads();

        // ---- GEMM2 (K=128): A3 = relu(A2 @ W2 + b2) -> reuse Xs ----
        gemm_tile<8, WPITCH>(sA2, sW2, wr, wc, lane, d);
        epi_relu_bf16<XPITCH>(sm + SM_XS, b2s, d, wr, wc, lane);
        __syncthreads();

        // ---- GEMM3 (K=128): D3 = A3 @ W3 (bias added during scatter) ----
        gemm_tile<8, XPITCH>(sXS, sW3, wr, wc, lane, d);
        __syncthreads();   // all warps done reading A3 before staging overwrites

        // fp32 staging into Xs (pitch 528B = 132 floats)
        {
            const int g = lane >> 2, q = lane & 3;
#pragma unroll
            for (int mi = 0; mi < 2; mi++) {
                const int rA = wr * 32 + mi * 16 + g;
#pragma unroll
                for (int ni = 0; ni < 4; ni++) {
                    const int c = wc * 32 + ni * 8 + 2 * q;
                    *(float2*)(sm + SM_XS + rA * XPITCH + c * 4) =
                        make_float2(d[mi][ni][0], d[mi][ni][1]);
                    *(float2*)(sm + SM_XS + (rA + 8) * XPITCH + c * 4) =
                        make_float2(d[mi][ni][2], d[mi][ni][3]);
                }
            }
        }
        __syncthreads();

        // ---- vectorized scatter-add: g_agg[dst] += D3 + b3 ----
        {
            const int row = tid >> 2, cg = (tid & 3) * 32;
            const int dst = idxs[64 + row];
            float* base = g_agg + (size_t)dst * 128 + cg;
            const float* srow = (const float*)(sm + SM_XS + row * XPITCH) + cg;
#pragma unroll
            for (int j = 0; j < 8; j++) {
                float4 v  = *(const float4*)(srow + 4 * j);
                float4 bb = *(const float4*)&b3s[cg + 4 * j];
                red_add_v4(base + 4 * j, v.x + bb.x, v.y + bb.y,
                           v.z + bb.z, v.w + bb.w);
            }
        }
        __syncthreads();   // protect idxs/Xs before next tile
    }
}

// ---------------------------------------------------------------------------
// Node MLP (fp32 FFMA): out = relu([h, agg] @ Wn1 + bn1) @ Wn2 + bn2
// ---------------------------------------------------------------------------
__global__ __launch_bounds__(NT, 1) void k_node(
    const float* __restrict__ h,
    const float* __restrict__ Wn1, const float* __restrict__ bn1,
    const float* __restrict__ Wn2, const float* __restrict__ bn2,
    float* __restrict__ out) {
    extern __shared__ float smf[];
    float* Wn1s = smf;                 // 256*128
    float* Wn2s = Wn1s + 256 * 128;    // 128*128
    float* bn1s = Wn2s + 128 * 128;    // 128
    float* bn2s = bn1s + 128;          // 128
    float* Xs   = bn2s + 128;          // 64*128

    const int tid = threadIdx.x;
    for (int i = tid; i < 256 * 128 / 4; i += NT)
        ((float4*)Wn1s)[i] = ((const float4*)Wn1)[i];
    for (int i = tid; i < 128 * 128 / 4; i += NT)
        ((float4*)Wn2s)[i] = ((const float4*)Wn2)[i];
    if (tid < 128) { bn1s[tid] = bn1[tid]; bn2s[tid] = bn2[tid]; }

    const int tx = tid & 31, ty = tid >> 5;
    const float4* h4 = (const float4*)h;
    const float4* a4 = (const float4*)g_agg;
    const int numTiles = (V_N + TM - 1) / TM;
    const float4 z = make_float4(0.f, 0.f, 0.f, 0.f);

    for (int tile = blockIdx.x; tile < numTiles; tile += gridDim.x) {
        const int n0 = tile * TM;
        float acc[8][4];
#pragma unroll
        for (int i = 0; i < 8; i++)
#pragma unroll
            for (int c = 0; c < 4; c++) acc[i][c] = 0.f;

        __syncthreads();
        for (int i = tid; i < TM * 32; i += NT) {
            int rr = i >> 5, j = i & 31;
            int node = n0 + rr;
            ((float4*)Xs)[i] = (node < V_N) ? h4[(size_t)node * 32 + j] : z;
        }
        __syncthreads();
        {
            const float* xb = Xs + ty * 8 * 128;
#pragma unroll 4
            for (int k = 0; k < 128; k++) {
                float4 w = ((const float4*)(Wn1s + k * 128))[tx];
#pragma unroll
                for (int i = 0; i < 8; i++) {
                    float x = xb[i * 128 + k];
                    acc[i][0] = fmaf(x, w.x, acc[i][0]);
                    acc[i][1] = fmaf(x, w.y, acc[i][1]);
                    acc[i][2] = fmaf(x, w.z, acc[i][2]);
                    acc[i][3] = fmaf(x, w.w, acc[i][3]);
                }
            }
        }
        __syncthreads();
        for (int i = tid; i < TM * 32; i += NT) {
            int rr = i >> 5, j = i & 31;
            int node = n0 + rr;
            ((float4*)Xs)[i] = (node < V_N) ? a4[(size_t)node * 32 + j] : z;
        }
        __syncthreads();
        {
            const float* xb = Xs + ty * 8 * 128;
#pragma unroll 4
            for (int k = 0; k < 128; k++) {
                float4 w = ((const float4*)(Wn1s + (128 + k) * 128))[tx];
#pragma unroll
                for (int i = 0; i < 8; i++) {
                    float x = xb[i * 128 + k];
                    acc[i][0] = fmaf(x, w.x, acc[i][0]);
                    acc[i][1] = fmaf(x, w.y, acc[i][1]);
                    acc[i][2] = fmaf(x, w.z, acc[i][2]);
                    acc[i][3] = fmaf(x, w.w, acc[i][3]);
                }
            }
        }
        __syncthreads();
        float4 b1v = ((const float4*)bn1s)[tx];
#pragma unroll
        for (int i = 0; i < 8; i++) {
            float4 o;
            o.x = fmaxf(acc[i][0] + b1v.x, 0.f);
            o.y = fmaxf(acc[i][1] + b1v.y, 0.f);
            o.z = fmaxf(acc[i][2] + b1v.z, 0.f);
            o.w = fmaxf(acc[i][3] + b1v.w, 0.f);
            ((float4*)(Xs + (ty * 8 + i) * 128))[tx] = o;
        }
        __syncthreads();
#pragma unroll
        for (int i = 0; i < 8; i++)
#pragma unroll
            for (int c = 0; c < 4; c++) acc[i][c] = 0.f;
        {
            const float* xb = Xs + ty * 8 * 128;
#pragma unroll 4
            for (int k = 0; k < 128; k++) {
                float4 w = ((const float4*)(Wn2s + k * 128))[tx];
#pragma unroll
                for (int i = 0; i < 8; i++) {
                    float x = xb[i * 128 + k];
                    acc[i][0] = fmaf(x, w.x, acc[i][0]);
                    acc[i][1] = fmaf(x, w.y, acc[i][1]);
                    acc[i][2] = fmaf(x, w.z, acc[i][2]);
                    acc[i][3] = fmaf(x, w.w, acc[i][3]);
                }
            }
        }
        float4 b2v = ((const float4*)bn2s)[tx];
#pragma unroll
        for (int i = 0; i < 8; i++) {
            int node = n0 + ty * 8 + i;
            if (node < V_N) {
                float4 o;
                o.x = acc[i][0] + b2v.x;
                o.y = acc[i][1] + b2v.y;
                o.z = acc[i][2] + b2v.z;
                o.w = acc[i][3] + b2v.w;
                ((float4*)(out + (size_t)node * 128))[tx] = o;
            }
        }
    }
}

// ---------------------------------------------------------------------------
extern "C" void kernel_launch(void* const* d_in, const int* in_sizes, int n_in,
                              void* d_out, int out_size) {
    const float* h   = (const float*)d_in[0];
    const int*   ei  = (const int*)d_in[1];   // int32 (JAX x64 disabled)
    const float* W1  = (const float*)d_in[2];
    const float* b1  = (const float*)d_in[3];
    const float* W2  = (const float*)d_in[4];
    const float* b2  = (const float*)d_in[5];
    const float* W3  = (const float*)d_in[6];
    const float* b3  = (const float*)d_in[7];
    const float* Wn1 = (const float*)d_in[8];
    const float* bn1 = (const float*)d_in[9];
    const float* Wn2 = (const float*)d_in[10];
    const float* bn2 = (const float*)d_in[11];
    float*       out = (float*)d_out;

    const int smemE = SM_EDGE_TOTAL;                                 // 192512
    const int smemN = (256 * 128 + 128 * 128 + 256 + TM * 128) * 4;  // 230400

    cudaFuncSetAttribute(k_edge, cudaFuncAttributeMaxDynamicSharedMemorySize, smemE);
    cudaFuncSetAttribute(k_node, cudaFuncAttributeMaxDynamicSharedMemorySize, smemN);

    k_zero_agg<<<512, 256>>>();
    k_edge<<<148, NT, smemE>>>(h, ei, W1, b1, W2, b2, W3, b3);
    k_node<<<152, NT, smemN>>>(h, Wn1, bn1, Wn2, bn2, out);
}

// round 7
// speedup vs baseline: 1.2335x; 1.2335x over previous
#include <cuda_runtime.h>
#include <cuda_bf16.h>
#include <cstdint>

// Problem constants (fixed shapes)
#define V_N 50000
#define E_N 800000
#define TM  64     // node-kernel rows per tile
#define NT  256

// Scratch (static device arrays — no runtime allocation)
__device__ float g_agg[(size_t)V_N * 128];   // scatter-add accumulator (25.6 MB)
__device__ float g_PQ[(size_t)V_N * 256];    // [P | Q] per node (51.2 MB)

// ============================================================================
// Warp-level MMA helpers (base PTX: ldmatrix sm_75+, mma.sync bf16 sm_80+)
// ============================================================================
__device__ __forceinline__ uint32_t smem_u32(const void* p) {
    uint32_t a;
    asm("{ .reg .u64 t; cvta.to.shared.u64 t, %1; cvt.u32.u64 %0, t; }"
        : "=r"(a) : "l"(p));
    return a;
}
__device__ __forceinline__ void ldsm_x4(uint32_t* r, uint32_t addr) {
    asm volatile("ldmatrix.sync.aligned.m8n8.x4.shared.b16 {%0,%1,%2,%3}, [%4];"
                 : "=r"(r[0]), "=r"(r[1]), "=r"(r[2]), "=r"(r[3]) : "r"(addr));
}
__device__ __forceinline__ void ldsm_x4_t(uint32_t* r, uint32_t addr) {
    asm volatile("ldmatrix.sync.aligned.m8n8.x4.trans.shared.b16 {%0,%1,%2,%3}, [%4];"
                 : "=r"(r[0]), "=r"(r[1]), "=r"(r[2]), "=r"(r[3]) : "r"(addr));
}
__device__ __forceinline__ void mma_bf16(float* d, const uint32_t* a, const uint32_t* b) {
    asm volatile(
        "mma.sync.aligned.m16n8k16.row.col.f32.bf16.bf16.f32 "
        "{%0,%1,%2,%3}, {%4,%5,%6,%7}, {%8,%9}, {%0,%1,%2,%3};"
        : "+f"(d[0]), "+f"(d[1]), "+f"(d[2]), "+f"(d[3])
        : "r"(a[0]), "r"(a[1]), "r"(a[2]), "r"(a[3]), "r"(b[0]), "r"(b[1]));
}
__device__ __forceinline__ uint32_t pack2(float a, float b) {
    __nv_bfloat162 p = __floats2bfloat162_rn(a, b);
    return *(uint32_t*)&p;
}
__device__ __forceinline__ void red_add_v2(float* p, float a, float b) {
    asm volatile("red.global.add.v2.f32 [%0], {%1, %2};"
                 :: "l"(p), "f"(a), "f"(b) : "memory");
}

#define WPITCH 272   // bf16 tile pitch for 128-col matrices (odd multiple of 16B)
#define BPITCH 528   // bf16 tile pitch for 256-col matrix (k_pq weights)

// Warp-tile GEMM: D(32x32) += A(32xK)@W, A rows at wr*32, W cols at wc*32.
template <int NK, int AP>
__device__ __forceinline__ void gemm_tile(uint32_t abase, uint32_t wbase,
                                          int wr, int wc, int lane,
                                          float d[2][4][4]) {
    const int l15 = lane & 15;
    const int kh  = (lane >> 4) << 3;   // 0 or 8
#pragma unroll
    for (int mi = 0; mi < 2; mi++)
#pragma unroll
        for (int ni = 0; ni < 4; ni++)
#pragma unroll
            for (int x = 0; x < 4; x++) d[mi][ni][x] = 0.f;

#pragma unroll
    for (int ks = 0; ks < NK; ks++) {
        uint32_t a[2][4], b[4][2];
#pragma unroll
        for (int mi = 0; mi < 2; mi++) {
            uint32_t addr = abase + (uint32_t)((wr * 32 + mi * 16 + l15) * AP +
                                               (ks * 16 + kh) * 2);
            ldsm_x4(a[mi], addr);
        }
#pragma unroll
        for (int nj = 0; nj < 2; nj++) {
            uint32_t addr = wbase + (uint32_t)((ks * 16 + l15) * WPITCH +
                                               (wc * 32 + nj * 16 + kh) * 2);
            uint32_t t[4];
            ldsm_x4_t(t, addr);
            b[2 * nj][0] = t[0]; b[2 * nj][1] = t[1];
            b[2 * nj + 1][0] = t[2]; b[2 * nj + 1][1] = t[3];
        }
#pragma unroll
        for (int mi = 0; mi < 2; mi++)
#pragma unroll
            for (int ni = 0; ni < 4; ni++)
                mma_bf16(d[mi][ni], a[mi], b[ni]);
    }
}

// Epilogue: relu(d + bias) -> bf16 tile at dstbase (pitch P bytes)
template <int P>
__device__ __forceinline__ void epi_relu_bf16(char* dstbase, const float* bias,
                                              float d[2][4][4],
                                              int wr, int wc, int lane) {
    const int g = lane >> 2, q = lane & 3;
#pragma unroll
    for (int mi = 0; mi < 2; mi++) {
        const int rA = wr * 32 + mi * 16 + g;
#pragma unroll
        for (int ni = 0; ni < 4; ni++) {
            const int c = wc * 32 + ni * 8 + 2 * q;
            float2 bb = *(const float2*)&bias[c];
            float v0 = fmaxf(d[mi][ni][0] + bb.x, 0.f);
            float v1 = fmaxf(d[mi][ni][1] + bb.y, 0.f);
            float v2 = fmaxf(d[mi][ni][2] + bb.x, 0.f);
            float v3 = fmaxf(d[mi][ni][3] + bb.y, 0.f);
            *(uint32_t*)(dstbase + rA * P + c * 2)       = pack2(v0, v1);
            *(uint32_t*)(dstbase + (rA + 8) * P + c * 2) = pack2(v2, v3);
        }
    }
}

// ---------------------------------------------------------------------------
// Zero the aggregation buffer
// ---------------------------------------------------------------------------
__global__ void k_zero_agg() {
    const int n4 = V_N * 128 / 4;
    float4 z = make_float4(0.f, 0.f, 0.f, 0.f);
    for (int i = blockIdx.x * blockDim.x + threadIdx.x; i < n4;
         i += gridDim.x * blockDim.x)
        ((float4*)g_agg)[i] = z;
}

// ---------------------------------------------------------------------------
// Precompute per-node first-layer terms:
//   g_PQ[v][0:128]   = h[v] @ W1[0:128, :]    (src half)
//   g_PQ[v][128:256] = h[v] @ W1[128:256, :]  (dst half)
// Tile: 64 nodes x 256 outputs, K=128. 8 warps, warp tile 32x64.
// ---------------------------------------------------------------------------
#define PQ_W 0                 // 128 x 528B = 67584
#define PQ_H 67584             // 64 x 272B = 17408
#define SM_PQ_TOTAL 84992

__global__ __launch_bounds__(NT, 2) void k_pq(
    const float* __restrict__ h, const float* __restrict__ W1)
{
    extern __shared__ __align__(16) char sm[];
    const uint32_t sbase = smem_u32(sm);
    const uint32_t sW = sbase + PQ_W, sH = sbase + PQ_H;
    const int tid = threadIdx.x, wid = tid >> 5, lane = tid & 31;
    const int wr = wid & 1, wc = wid >> 1;
    const int l15 = lane & 15, kh = (lane >> 4) << 3;
    const int g = lane >> 2, q = lane & 3;

    // Stage W1 -> B layout: B[k][n] = (n<128) ? W1[k][n] : W1[128+k][n-128]
    for (int i = tid; i < 128 * 256; i += NT) {
        int k = i >> 8, n = i & 255;
        float w = (n < 128) ? W1[k * 128 + n] : W1[(128 + k) * 128 + (n - 128)];
        *(__nv_bfloat16*)(sm + PQ_W + k * BPITCH + n * 2) = __float2bfloat16(w);
    }
    __syncthreads();

    const float4* h4 = (const float4*)h;
    const int numTiles = (V_N + 63) / 64;   // 782

    for (int tile = blockIdx.x; tile < numTiles; tile += gridDim.x) {
        const int n0 = tile * 64;
        __syncthreads();
        // Stage h rows (bf16, pitch 272)
        for (int i = tid; i < 64 * 32; i += NT) {
            int r = i >> 5, j = i & 31;
            int node = n0 + r;
            float4 v = (node < V_N) ? h4[(size_t)node * 32 + j]
                                    : make_float4(0.f, 0.f, 0.f, 0.f);
            uint2 u; u.x = pack2(v.x, v.y); u.y = pack2(v.z, v.w);
            *(uint2*)(sm + PQ_H + r * WPITCH + j * 8) = u;
        }
        __syncthreads();

        float d[2][8][4];
#pragma unroll
        for (int mi = 0; mi < 2; mi++)
#pragma unroll
            for (int ni = 0; ni < 8; ni++)
#pragma unroll
                for (int x = 0; x < 4; x++) d[mi][ni][x] = 0.f;

#pragma unroll
        for (int ks = 0; ks < 8; ks++) {
            uint32_t a[2][4], b[8][2];
#pragma unroll
            for (int mi = 0; mi < 2; mi++) {
                uint32_t addr = sH + (uint32_t)((wr * 32 + mi * 16 + l15) * WPITCH +
                                                (ks * 16 + kh) * 2);
                ldsm_x4(a[mi], addr);
            }
#pragma unroll
            for (int nj = 0; nj < 4; nj++) {
                uint32_t addr = sW + (uint32_t)((ks * 16 + l15) * BPITCH +
                                                (wc * 64 + nj * 16 + kh) * 2);
                uint32_t t[4];
                ldsm_x4_t(t, addr);
                b[2 * nj][0] = t[0]; b[2 * nj][1] = t[1];
                b[2 * nj + 1][0] = t[2]; b[2 * nj + 1][1] = t[3];
            }
#pragma unroll
            for (int mi = 0; mi < 2; mi++)
#pragma unroll
                for (int ni = 0; ni < 8; ni++)
                    mma_bf16(d[mi][ni], a[mi], b[ni]);
        }

        // Store fp32 P|Q
#pragma unroll
        for (int mi = 0; mi < 2; mi++) {
            const int rA = wr * 32 + mi * 16 + g;
            const int nodeA = n0 + rA, nodeB = nodeA + 8;
#pragma unroll
            for (int ni = 0; ni < 8; ni++) {
                const int c = wc * 64 + ni * 8 + 2 * q;
                if (nodeA < V_N)
                    *(float2*)&g_PQ[(size_t)nodeA * 256 + c] =
                        make_float2(d[mi][ni][0], d[mi][ni][1]);
                if (nodeB < V_N)
                    *(float2*)&g_PQ[(size_t)nodeB * 256 + c] =
                        make_float2(d[mi][ni][2], d[mi][ni][3]);
            }
        }
    }
}

// ---------------------------------------------------------------------------
// Edge kernel: A2 = relu(P[src]+Q[dst]+b1);  A3 = relu(A2@W2+b2);
//              scatter g_agg[dst] += A3@W3 + b3   (direct from fragments)
// 64-edge tiles, 8 warps (2x4), ~104KB smem -> 2 blocks/SM.
// ---------------------------------------------------------------------------
#define SM_IDX 0        // 128 ints
#define SM_BB1 512
#define SM_BB2 1024
#define SM_BB3 1536
#define SM_W2  2048     // 128 x 272 = 34816
#define SM_W3  36864    // 34816
#define SM_A2  71680    // 64 x 272 = 17408
#define SM_A3  89088    // 17408
#define SM_EDGE_TOTAL 106496

__global__ __launch_bounds__(NT, 2) void k_edge(
    const int* __restrict__ ei,
    const float* __restrict__ b1,
    const float* __restrict__ W2, const float* __restrict__ b2,
    const float* __restrict__ W3, const float* __restrict__ b3)
{
    extern __shared__ __align__(16) char sm[];
    int*   idxs = (int*)(sm + SM_IDX);
    float* b1s  = (float*)(sm + SM_BB1);
    float* b2s  = (float*)(sm + SM_BB2);
    float* b3s  = (float*)(sm + SM_BB3);
    const uint32_t sbase = smem_u32(sm);
    const uint32_t sW2 = sbase + SM_W2, sW3 = sbase + SM_W3;
    const uint32_t sA2 = sbase + SM_A2, sA3 = sbase + SM_A3;

    const int tid = threadIdx.x, wid = tid >> 5, lane = tid & 31;
    const int wr = wid & 1, wc = wid >> 1;
    const int g = lane >> 2, q = lane & 3;

    // Stage W2/W3 bf16 + biases
    for (int i = tid; i < 128 * 128; i += NT) {
        int k = i >> 7, n = i & 127;
        *(__nv_bfloat16*)(sm + SM_W2 + k * WPITCH + n * 2) = __float2bfloat16(W2[i]);
        *(__nv_bfloat16*)(sm + SM_W3 + k * WPITCH + n * 2) = __float2bfloat16(W3[i]);
    }
    if (tid < 128) { b1s[tid] = b1[tid]; b2s[tid] = b2[tid]; b3s[tid] = b3[tid]; }
    __syncthreads();

    const float4* pq4 = (const float4*)g_PQ;
    float d[2][4][4];
    const int numTiles = E_N / 64;   // 12500

    for (int tile = blockIdx.x; tile < numTiles; tile += gridDim.x) {
        const int e0 = tile * 64;
        __syncthreads();   // protect idxs/A2 from previous tile's readers
        if (tid < 64)       idxs[tid] = ei[e0 + tid];
        else if (tid < 128) idxs[tid] = ei[E_N + e0 + (tid - 64)];
        __syncthreads();

        // ---- A2 = relu(P[src] + Q[dst] + b1), bf16 ----
        for (int i = tid; i < 64 * 32; i += NT) {
            int r = i >> 5, j = i & 31;
            int s = idxs[r], t = idxs[64 + r];
            float4 p = pq4[(size_t)s * 64 + j];
            float4 qv = pq4[(size_t)t * 64 + 32 + j];
            float4 bb = *(const float4*)&b1s[j * 4];
            float v0 = fmaxf(p.x + qv.x + bb.x, 0.f);
            float v1 = fmaxf(p.y + qv.y + bb.y, 0.f);
            float v2 = fmaxf(p.z + qv.z + bb.z, 0.f);
            float v3 = fmaxf(p.w + qv.w + bb.w, 0.f);
            uint2 u; u.x = pack2(v0, v1); u.y = pack2(v2, v3);
            *(uint2*)(sm + SM_A2 + r * WPITCH + j * 8) = u;
        }
        __syncthreads();

        // ---- GEMM2 (K=128): A3 = relu(A2 @ W2 + b2) ----
        gemm_tile<8, WPITCH>(sA2, sW2, wr, wc, lane, d);
        epi_relu_bf16<WPITCH>(sm + SM_A3, b2s, d, wr, wc, lane);
        __syncthreads();

        // ---- GEMM3 (K=128): scatter g_agg[dst] += A3 @ W3 + b3 ----
        gemm_tile<8, WPITCH>(sA3, sW3, wr, wc, lane, d);
#pragma unroll
        for (int mi = 0; mi < 2; mi++) {
            const int rA = wr * 32 + mi * 16 + g;
            const int d0 = idxs[64 + rA], d1 = idxs[64 + rA + 8];
#pragma unroll
            for (int ni = 0; ni < 4; ni++) {
                const int c = wc * 32 + ni * 8 + 2 * q;
                float2 bb = *(const float2*)&b3s[c];
                red_add_v2(g_agg + (size_t)d0 * 128 + c,
                           d[mi][ni][0] + bb.x, d[mi][ni][1] + bb.y);
                red_add_v2(g_agg + (size_t)d1 * 128 + c,
                           d[mi][ni][2] + bb.x, d[mi][ni][3] + bb.y);
            }
        }
    }
}

// ---------------------------------------------------------------------------
// Node MLP (fp32 FFMA): out = relu([h, agg] @ Wn1 + bn1) @ Wn2 + bn2
// ---------------------------------------------------------------------------
__global__ __launch_bounds__(NT, 1) void k_node(
    const float* __restrict__ h,
    const float* __restrict__ Wn1, const float* __restrict__ bn1,
    const float* __restrict__ Wn2, const float* __restrict__ bn2,
    float* __restrict__ out) {
    extern __shared__ float smf[];
    float* Wn1s = smf;                 // 256*128
    float* Wn2s = Wn1s + 256 * 128;    // 128*128
    float* bn1s = Wn2s + 128 * 128;    // 128
    float* bn2s = bn1s + 128;          // 128
    float* Xs   = bn2s + 128;          // 64*128

    const int tid = threadIdx.x;
    for (int i = tid; i < 256 * 128 / 4; i += NT)
        ((float4*)Wn1s)[i] = ((const float4*)Wn1)[i];
    for (int i = tid; i < 128 * 128 / 4; i += NT)
        ((float4*)Wn2s)[i] = ((const float4*)Wn2)[i];
    if (tid < 128) { bn1s[tid] = bn1[tid]; bn2s[tid] = bn2[tid]; }

    const int tx = tid & 31, ty = tid >> 5;
    const float4* h4 = (const float4*)h;
    const float4* a4 = (const float4*)g_agg;
    const int numTiles = (V_N + TM - 1) / TM;
    const float4 z = make_float4(0.f, 0.f, 0.f, 0.f);

    for (int tile = blockIdx.x; tile < numTiles; tile += gridDim.x) {
        const int n0 = tile * TM;
        float acc[8][4];
#pragma unroll
        for (int i = 0; i < 8; i++)
#pragma unroll
            for (int c = 0; c < 4; c++) acc[i][c] = 0.f;

        __syncthreads();
        for (int i = tid; i < TM * 32; i += NT) {
            int rr = i >> 5, j = i & 31;
            int node = n0 + rr;
            ((float4*)Xs)[i] = (node < V_N) ? h4[(size_t)node * 32 + j] : z;
        }
        __syncthreads();
        {
            const float* xb = Xs + ty * 8 * 128;
#pragma unroll 4
            for (int k = 0; k < 128; k++) {
                float4 w = ((const float4*)(Wn1s + k * 128))[tx];
#pragma unroll
                for (int i = 0; i < 8; i++) {
                    float x = xb[i * 128 + k];
                    acc[i][0] = fmaf(x, w.x, acc[i][0]);
                    acc[i][1] = fmaf(x, w.y, acc[i][1]);
                    acc[i][2] = fmaf(x, w.z, acc[i][2]);
                    acc[i][3] = fmaf(x, w.w, acc[i][3]);
                }
            }
        }
        __syncthreads();
        for (int i = tid; i < TM * 32; i += NT) {
            int rr = i >> 5, j = i & 31;
            int node = n0 + rr;
            ((float4*)Xs)[i] = (node < V_N) ? a4[(size_t)node * 32 + j] : z;
        }
        __syncthreads();
        {
            const float* xb = Xs + ty * 8 * 128;
#pragma unroll 4
            for (int k = 0; k < 128; k++) {
                float4 w = ((const float4*)(Wn1s + (128 + k) * 128))[tx];
#pragma unroll
                for (int i = 0; i < 8; i++) {
                    float x = xb[i * 128 + k];
                    acc[i][0] = fmaf(x, w.x, acc[i][0]);
                    acc[i][1] = fmaf(x, w.y, acc[i][1]);
                    acc[i][2] = fmaf(x, w.z, acc[i][2]);
                    acc[i][3] = fmaf(x, w.w, acc[i][3]);
                }
            }
        }
        __syncthreads();
        float4 b1v = ((const float4*)bn1s)[tx];
#pragma unroll
        for (int i = 0; i < 8; i++) {
            float4 o;
            o.x = fmaxf(acc[i][0] + b1v.x, 0.f);
            o.y = fmaxf(acc[i][1] + b1v.y, 0.f);
            o.z = fmaxf(acc[i][2] + b1v.z, 0.f);
            o.w = fmaxf(acc[i][3] + b1v.w, 0.f);
            ((float4*)(Xs + (ty * 8 + i) * 128))[tx] = o;
        }
        __syncthreads();
#pragma unroll
        for (int i = 0; i < 8; i++)
#pragma unroll
            for (int c = 0; c < 4; c++) acc[i][c] = 0.f;
        {
            const float* xb = Xs + ty * 8 * 128;
#pragma unroll 4
            for (int k = 0; k < 128; k++) {
                float4 w = ((const float4*)(Wn2s + k * 128))[tx];
#pragma unroll
                for (int i = 0; i < 8; i++) {
                    float x = xb[i * 128 + k];
                    acc[i][0] = fmaf(x, w.x, acc[i][0]);
                    acc[i][1] = fmaf(x, w.y, acc[i][1]);
                    acc[i][2] = fmaf(x, w.z, acc[i][2]);
                    acc[i][3] = fmaf(x, w.w, acc[i][3]);
                }
            }
        }
        float4 b2v = ((const float4*)bn2s)[tx];
#pragma unroll
        for (int i = 0; i < 8; i++) {
            int node = n0 + ty * 8 + i;
            if (node < V_N) {
                float4 o;
                o.x = acc[i][0] + b2v.x;
                o.y = acc[i][1] + b2v.y;
                o.z = acc[i][2] + b2v.z;
                o.w = acc[i][3] + b2v.w;
                ((float4*)(out + (size_t)node * 128))[tx] = o;
            }
        }
    }
}

// ---------------------------------------------------------------------------
extern "C" void kernel_launch(void* const* d_in, const int* in_sizes, int n_in,
                              void* d_out, int out_size) {
    const float* h   = (const float*)d_in[0];
    const int*   ei  = (const int*)d_in[1];   // int32 (JAX x64 disabled)
    const float* W1  = (const float*)d_in[2];
    const float* b1  = (const float*)d_in[3];
    const float* W2  = (const float*)d_in[4];
    const float* b2  = (const float*)d_in[5];
    const float* W3  = (const float*)d_in[6];
    const float* b3  = (const float*)d_in[7];
    const float* Wn1 = (const float*)d_in[8];
    const float* bn1 = (const float*)d_in[9];
    const float* Wn2 = (const float*)d_in[10];
    const float* bn2 = (const float*)d_in[11];
    float*       out = (float*)d_out;

    const int smemP = SM_PQ_TOTAL;                                   // 84992
    const int smemE = SM_EDGE_TOTAL;                                 // 106496
    const int smemN = (256 * 128 + 128 * 128 + 256 + TM * 128) * 4;  // 230400

    cudaFuncSetAttribute(k_pq,   cudaFuncAttributeMaxDynamicSharedMemorySize, smemP);
    cudaFuncSetAttribute(k_edge, cudaFuncAttributeMaxDynamicSharedMemorySize, smemE);
    cudaFuncSetAttribute(k_node, cudaFuncAttributeMaxDynamicSharedMemorySize, smemN);

    k_zero_agg<<<512, 256>>>();
    k_pq<<<296, NT, smemP>>>(h, W1);
    k_edge<<<296, NT, smemE>>>(ei, b1, W2, b2, W3, b3);
    k_node<<<152, NT, smemN>>>(h, Wn1, bn1, Wn2, bn2, out);
}

// round 8
// speedup vs baseline: 1.8787x; 1.5231x over previous
#include <cuda_runtime.h>
#include <cuda_bf16.h>
#include <cstdint>

// Problem constants (fixed shapes)
#define V_N 50000
#define E_N 800000

// Scratch (static device arrays — no runtime allocation)
__device__ float g_agg[(size_t)V_N * 128];   // scatter-add accumulator (25.6 MB)
__device__ float g_PQ[(size_t)V_N * 256];    // [P | Q] per node (51.2 MB)
__device__ float g_R[(size_t)V_N * 128];     // h @ Wn1_top (25.6 MB, near-fp32)

// ============================================================================
// Warp-level MMA helpers (base PTX: ldmatrix sm_75+, mma.sync bf16 sm_80+)
// ============================================================================
__device__ __forceinline__ uint32_t smem_u32(const void* p) {
    uint32_t a;
    asm("{ .reg .u64 t; cvta.to.shared.u64 t, %1; cvt.u32.u64 %0, t; }"
        : "=r"(a) : "l"(p));
    return a;
}
__device__ __forceinline__ void ldsm_x4(uint32_t* r, uint32_t addr) {
    asm volatile("ldmatrix.sync.aligned.m8n8.x4.shared.b16 {%0,%1,%2,%3}, [%4];"
                 : "=r"(r[0]), "=r"(r[1]), "=r"(r[2]), "=r"(r[3]) : "r"(addr));
}
__device__ __forceinline__ void ldsm_x4_t(uint32_t* r, uint32_t addr) {
    asm volatile("ldmatrix.sync.aligned.m8n8.x4.trans.shared.b16 {%0,%1,%2,%3}, [%4];"
                 : "=r"(r[0]), "=r"(r[1]), "=r"(r[2]), "=r"(r[3]) : "r"(addr));
}
__device__ __forceinline__ void mma_bf16(float* d, const uint32_t* a, const uint32_t* b) {
    asm volatile(
        "mma.sync.aligned.m16n8k16.row.col.f32.bf16.bf16.f32 "
        "{%0,%1,%2,%3}, {%4,%5,%6,%7}, {%8,%9}, {%0,%1,%2,%3};"
        : "+f"(d[0]), "+f"(d[1]), "+f"(d[2]), "+f"(d[3])
        : "r"(a[0]), "r"(a[1]), "r"(a[2]), "r"(a[3]), "r"(b[0]), "r"(b[1]));
}
__device__ __forceinline__ uint32_t pack2(float a, float b) {
    __nv_bfloat162 p = __floats2bfloat162_rn(a, b);
    return *(uint32_t*)&p;
}
__device__ __forceinline__ void red_add_v2(float* p, float a, float b) {
    asm volatile("red.global.add.v2.f32 [%0], {%1, %2};"
                 :: "l"(p), "f"(a), "f"(b) : "memory");
}

#define WPITCH 272   // bf16 tile pitch for 128-col matrices
#define BPITCH 528   // bf16 tile pitch for 256-col matrix (k_pq weights)

// Warp-tile GEMM (ACCUMULATES into d; caller zeroes):
// D(32x32) += A(32xK)@W, A rows at wr*32, W cols at wc*32.
template <int NK, int AP>
__device__ __forceinline__ void gemm_tile(uint32_t abase, uint32_t wbase,
                                          int wr, int wc, int lane,
                                          float d[2][4][4]) {
    const int l15 = lane & 15;
    const int kh  = (lane >> 4) << 3;   // 0 or 8
#pragma unroll
    for (int ks = 0; ks < NK; ks++) {
        uint32_t a[2][4], b[4][2];
#pragma unroll
        for (int mi = 0; mi < 2; mi++) {
            uint32_t addr = abase + (uint32_t)((wr * 32 + mi * 16 + l15) * AP +
                                               (ks * 16 + kh) * 2);
            ldsm_x4(a[mi], addr);
        }
#pragma unroll
        for (int nj = 0; nj < 2; nj++) {
            uint32_t addr = wbase + (uint32_t)((ks * 16 + l15) * WPITCH +
                                               (wc * 32 + nj * 16 + kh) * 2);
            uint32_t t[4];
            ldsm_x4_t(t, addr);
            b[2 * nj][0] = t[0]; b[2 * nj][1] = t[1];
            b[2 * nj + 1][0] = t[2]; b[2 * nj + 1][1] = t[3];
        }
#pragma unroll
        for (int mi = 0; mi < 2; mi++)
#pragma unroll
            for (int ni = 0; ni < 4; ni++)
                mma_bf16(d[mi][ni], a[mi], b[ni]);
    }
}
__device__ __forceinline__ void zero_d(float d[2][4][4]) {
#pragma unroll
    for (int mi = 0; mi < 2; mi++)
#pragma unroll
        for (int ni = 0; ni < 4; ni++)
#pragma unroll
            for (int x = 0; x < 4; x++) d[mi][ni][x] = 0.f;
}

// Epilogue: relu(d + bias) -> bf16 tile at dstbase (pitch P bytes)
template <int P>
__device__ __forceinline__ void epi_relu_bf16(char* dstbase, const float* bias,
                                              float d[2][4][4],
                                              int wr, int wc, int lane) {
    const int g = lane >> 2, q = lane & 3;
#pragma unroll
    for (int mi = 0; mi < 2; mi++) {
        const int rA = wr * 32 + mi * 16 + g;
#pragma unroll
        for (int ni = 0; ni < 4; ni++) {
            const int c = wc * 32 + ni * 8 + 2 * q;
            float2 bb = *(const float2*)&bias[c];
            float v0 = fmaxf(d[mi][ni][0] + bb.x, 0.f);
            float v1 = fmaxf(d[mi][ni][1] + bb.y, 0.f);
            float v2 = fmaxf(d[mi][ni][2] + bb.x, 0.f);
            float v3 = fmaxf(d[mi][ni][3] + bb.y, 0.f);
            *(uint32_t*)(dstbase + rA * P + c * 2)       = pack2(v0, v1);
            *(uint32_t*)(dstbase + (rA + 8) * P + c * 2) = pack2(v2, v3);
        }
    }
}

// ---------------------------------------------------------------------------
// Zero the aggregation buffer
// ---------------------------------------------------------------------------
__global__ void k_zero_agg() {
    const int n4 = V_N * 128 / 4;
    float4 z = make_float4(0.f, 0.f, 0.f, 0.f);
    for (int i = blockIdx.x * blockDim.x + threadIdx.x; i < n4;
         i += gridDim.x * blockDim.x)
        ((float4*)g_agg)[i] = z;
}

// ---------------------------------------------------------------------------
// k_pq: per-node first-layer terms (bf16 single precision — edge path).
//   g_PQ[v][0:128]   = h[v] @ W1[0:128, :]
//   g_PQ[v][128:256] = h[v] @ W1[128:256, :]
// ---------------------------------------------------------------------------
#define PQ_W 0                 // 128 x 528B = 67584
#define PQ_H 67584             // 64 x 272B = 17408
#define SM_PQ_TOTAL 84992

__global__ __launch_bounds__(256, 2) void k_pq(
    const float* __restrict__ h, const float* __restrict__ W1)
{
    extern __shared__ __align__(16) char sm[];
    const uint32_t sbase = smem_u32(sm);
    const uint32_t sW = sbase + PQ_W, sH = sbase + PQ_H;
    const int tid = threadIdx.x, wid = tid >> 5, lane = tid & 31;
    const int wr = wid & 1, wc = wid >> 1;
    const int l15 = lane & 15, kh = (lane >> 4) << 3;
    const int g = lane >> 2, q = lane & 3;

    for (int i = tid; i < 128 * 256; i += 256) {
        int k = i >> 8, n = i & 255;
        float w = (n < 128) ? W1[k * 128 + n] : W1[(128 + k) * 128 + (n - 128)];
        *(__nv_bfloat16*)(sm + PQ_W + k * BPITCH + n * 2) = __float2bfloat16(w);
    }
    __syncthreads();

    const float4* h4 = (const float4*)h;
    const int numTiles = (V_N + 63) / 64;   // 782

    for (int tile = blockIdx.x; tile < numTiles; tile += gridDim.x) {
        const int n0 = tile * 64;
        __syncthreads();
        for (int i = tid; i < 64 * 32; i += 256) {
            int r = i >> 5, j = i & 31;
            int node = n0 + r;
            float4 v = (node < V_N) ? h4[(size_t)node * 32 + j]
                                    : make_float4(0.f, 0.f, 0.f, 0.f);
            uint2 u; u.x = pack2(v.x, v.y); u.y = pack2(v.z, v.w);
            *(uint2*)(sm + PQ_H + r * WPITCH + j * 8) = u;
        }
        __syncthreads();

        float d[2][8][4];
#pragma unroll
        for (int mi = 0; mi < 2; mi++)
#pragma unroll
            for (int ni = 0; ni < 8; ni++)
#pragma unroll
                for (int x = 0; x < 4; x++) d[mi][ni][x] = 0.f;

#pragma unroll
        for (int ks = 0; ks < 8; ks++) {
            uint32_t a[2][4], b[8][2];
#pragma unroll
            for (int mi = 0; mi < 2; mi++) {
                uint32_t addr = sH + (uint32_t)((wr * 32 + mi * 16 + l15) * WPITCH +
                                                (ks * 16 + kh) * 2);
                ldsm_x4(a[mi], addr);
            }
#pragma unroll
            for (int nj = 0; nj < 4; nj++) {
                uint32_t addr = sW + (uint32_t)((ks * 16 + l15) * BPITCH +
                                                (wc * 64 + nj * 16 + kh) * 2);
                uint32_t t[4];
                ldsm_x4_t(t, addr);
                b[2 * nj][0] = t[0]; b[2 * nj][1] = t[1];
                b[2 * nj + 1][0] = t[2]; b[2 * nj + 1][1] = t[3];
            }
#pragma unroll
            for (int mi = 0; mi < 2; mi++)
#pragma unroll
                for (int ni = 0; ni < 8; ni++)
                    mma_bf16(d[mi][ni], a[mi], b[ni]);
        }

#pragma unroll
        for (int mi = 0; mi < 2; mi++) {
            const int rA = wr * 32 + mi * 16 + g;
            const int nodeA = n0 + rA, nodeB = nodeA + 8;
#pragma unroll
            for (int ni = 0; ni < 8; ni++) {
                const int c = wc * 64 + ni * 8 + 2 * q;
                if (nodeA < V_N)
                    *(float2*)&g_PQ[(size_t)nodeA * 256 + c] =
                        make_float2(d[mi][ni][0], d[mi][ni][1]);
                if (nodeB < V_N)
                    *(float2*)&g_PQ[(size_t)nodeB * 256 + c] =
                        make_float2(d[mi][ni][2], d[mi][ni][3]);
            }
        }
    }
}

// ---------------------------------------------------------------------------
// k_r: R = h @ Wn1_top in 3-term split-bf16 (near-fp32 accuracy).
//   h = hhi + hlo, W = whi + wlo;  R ≈ hhi@whi + hhi@wlo + hlo@whi
// 64-node tiles, 8 warps (2x4). smem 104448 -> 2 CTAs/SM.
// ---------------------------------------------------------------------------
#define R_WH 0          // 128 x 272 = 34816
#define R_WL 34816
#define R_HH 69632      // 64 x 272 = 17408
#define R_HL 87040
#define SM_R_TOTAL 104448

__global__ __launch_bounds__(256, 2) void k_r(
    const float* __restrict__ h, const float* __restrict__ Wn1)
{
    extern __shared__ __align__(16) char sm[];
    const uint32_t sbase = smem_u32(sm);
    const int tid = threadIdx.x, wid = tid >> 5, lane = tid & 31;
    const int wr = wid & 1, wc = wid >> 1;
    const int g = lane >> 2, q = lane & 3;

    // Wn1_top = Wn1[0:128][:], split hi/lo
    for (int i = tid; i < 128 * 128; i += 256) {
        int k = i >> 7, n = i & 127;
        float w = Wn1[k * 128 + n];
        __nv_bfloat16 whi = __float2bfloat16(w);
        float wlo = w - __bfloat162float(whi);
        *(__nv_bfloat16*)(sm + R_WH + k * WPITCH + n * 2) = whi;
        *(__nv_bfloat16*)(sm + R_WL + k * WPITCH + n * 2) = __float2bfloat16(wlo);
    }
    __syncthreads();

    const float4* h4 = (const float4*)h;
    const int numTiles = (V_N + 63) / 64;

    for (int tile = blockIdx.x; tile < numTiles; tile += gridDim.x) {
        const int n0 = tile * 64;
        __syncthreads();
        for (int i = tid; i < 64 * 32; i += 256) {
            int r = i >> 5, j = i & 31;
            int node = n0 + r;
            float4 v = (node < V_N) ? h4[(size_t)node * 32 + j]
                                    : make_float4(0.f, 0.f, 0.f, 0.f);
            __nv_bfloat16 h0 = __float2bfloat16(v.x), h1 = __float2bfloat16(v.y);
            __nv_bfloat16 h2 = __float2bfloat16(v.z), h3 = __float2bfloat16(v.w);
            uint2 uh, ul;
            uh.x = pack2(__bfloat162float(h0), __bfloat162float(h1));
            uh.y = pack2(__bfloat162float(h2), __bfloat162float(h3));
            // pack2 re-rounds but hi values are exactly representable
            ul.x = pack2(v.x - __bfloat162float(h0), v.y - __bfloat162float(h1));
            ul.y = pack2(v.z - __bfloat162float(h2), v.w - __bfloat162float(h3));
            *(uint2*)(sm + R_HH + r * WPITCH + j * 8) = uh;
            *(uint2*)(sm + R_HL + r * WPITCH + j * 8) = ul;
        }
        __syncthreads();

        float d[2][4][4];
        zero_d(d);
        gemm_tile<8, WPITCH>(sbase + R_HH, sbase + R_WH, wr, wc, lane, d);
        gemm_tile<8, WPITCH>(sbase + R_HH, sbase + R_WL, wr, wc, lane, d);
        gemm_tile<8, WPITCH>(sbase + R_HL, sbase + R_WH, wr, wc, lane, d);

#pragma unroll
        for (int mi = 0; mi < 2; mi++) {
            const int rA = wr * 32 + mi * 16 + g;
            const int nodeA = n0 + rA, nodeB = nodeA + 8;
#pragma unroll
            for (int ni = 0; ni < 4; ni++) {
                const int c = wc * 32 + ni * 8 + 2 * q;
                if (nodeA < V_N)
                    *(float2*)&g_R[(size_t)nodeA * 128 + c] =
                        make_float2(d[mi][ni][0], d[mi][ni][1]);
                if (nodeB < V_N)
                    *(float2*)&g_R[(size_t)nodeB * 128 + c] =
                        make_float2(d[mi][ni][2], d[mi][ni][3]);
            }
        }
    }
}

// ---------------------------------------------------------------------------
// k_edge: 128-edge tiles, 512 threads (16 warps, 4x4 grid of 32x32 tiles).
//   A2 = relu(P[src]+Q[dst]+b1); A3 = relu(A2@W2+b2);
//   scatter g_agg[dst] += A3@W3 + b3 (direct from fragments)
// ---------------------------------------------------------------------------
#define SM_IDX 0        // 256 ints = 1024
#define SM_BB1 1024
#define SM_BB2 1536
#define SM_BB3 2048
#define SM_W2  2560     // 128 x 272 = 34816
#define SM_W3  37376
#define SM_A2  72192
#define SM_A3  107008
#define SM_EDGE_TOTAL 141824

__global__ __launch_bounds__(512, 1) void k_edge(
    const int* __restrict__ ei,
    const float* __restrict__ b1,
    const float* __restrict__ W2, const float* __restrict__ b2,
    const float* __restrict__ W3, const float* __restrict__ b3)
{
    extern __shared__ __align__(16) char sm[];
    int*   idxs = (int*)(sm + SM_IDX);
    float* b1s  = (float*)(sm + SM_BB1);
    float* b2s  = (float*)(sm + SM_BB2);
    float* b3s  = (float*)(sm + SM_BB3);
    const uint32_t sbase = smem_u32(sm);
    const uint32_t sW2 = sbase + SM_W2, sW3 = sbase + SM_W3;
    const uint32_t sA2 = sbase + SM_A2, sA3 = sbase + SM_A3;

    const int tid = threadIdx.x, wid = tid >> 5, lane = tid & 31;
    const int wr = wid & 3, wc = wid >> 2;   // 4x4 warp grid
    const int g = lane >> 2, q = lane & 3;

    for (int i = tid; i < 128 * 128; i += 512) {
        int k = i >> 7, n = i & 127;
        *(__nv_bfloat16*)(sm + SM_W2 + k * WPITCH + n * 2) = __float2bfloat16(W2[i]);
        *(__nv_bfloat16*)(sm + SM_W3 + k * WPITCH + n * 2) = __float2bfloat16(W3[i]);
    }
    if (tid < 128) { b1s[tid] = b1[tid]; b2s[tid] = b2[tid]; b3s[tid] = b3[tid]; }
    __syncthreads();

    const float4* pq4 = (const float4*)g_PQ;
    float d[2][4][4];
    const int numTiles = E_N / 128;   // 6250

    for (int tile = blockIdx.x; tile < numTiles; tile += gridDim.x) {
        const int e0 = tile * 128;
        __syncthreads();   // protect idxs/A2 from previous tile's readers
        if (tid < 128)      idxs[tid] = ei[e0 + tid];
        else if (tid < 256) idxs[tid] = ei[E_N + e0 + (tid - 128)];
        __syncthreads();

        // ---- A2 = relu(P[src] + Q[dst] + b1), bf16 (128 x 128) ----
        for (int i = tid; i < 128 * 32; i += 512) {
            int r = i >> 5, j = i & 31;
            int s = idxs[r], t = idxs[128 + r];
            float4 p  = pq4[(size_t)s * 64 + j];
            float4 qv = pq4[(size_t)t * 64 + 32 + j];
            float4 bb = *(const float4*)&b1s[j * 4];
            float v0 = fmaxf(p.x + qv.x + bb.x, 0.f);
            float v1 = fmaxf(p.y + qv.y + bb.y, 0.f);
            float v2 = fmaxf(p.z + qv.z + bb.z, 0.f);
            float v3 = fmaxf(p.w + qv.w + bb.w, 0.f);
            uint2 u; u.x = pack2(v0, v1); u.y = pack2(v2, v3);
            *(uint2*)(sm + SM_A2 + r * WPITCH + j * 8) = u;
        }
        __syncthreads();

        // ---- GEMM2: A3 = relu(A2 @ W2 + b2) ----
        zero_d(d);
        gemm_tile<8, WPITCH>(sA2, sW2, wr, wc, lane, d);
        epi_relu_bf16<WPITCH>(sm + SM_A3, b2s, d, wr, wc, lane);
        __syncthreads();

        // ---- GEMM3: scatter g_agg[dst] += A3 @ W3 + b3 ----
        zero_d(d);
        gemm_tile<8, WPITCH>(sA3, sW3, wr, wc, lane, d);
#pragma unroll
        for (int mi = 0; mi < 2; mi++) {
            const int rA = wr * 32 + mi * 16 + g;
            const int d0 = idxs[128 + rA], d1 = idxs[128 + rA + 8];
#pragma unroll
            for (int ni = 0; ni < 4; ni++) {
                const int c = wc * 32 + ni * 8 + 2 * q;
                float2 bb = *(const float2*)&b3s[c];
                red_add_v2(g_agg + (size_t)d0 * 128 + c,
                           d[mi][ni][0] + bb.x, d[mi][ni][1] + bb.y);
                red_add_v2(g_agg + (size_t)d1 * 128 + c,
                           d[mi][ni][2] + bb.x, d[mi][ni][3] + bb.y);
            }
        }
    }
}

// ---------------------------------------------------------------------------
// k_node (tensor): T = relu(R + agg@Wn1_bot + bn1); out = T@Wn2 (3-term split).
// 128-node tiles, 512 threads (4x4 warp grid). smem 209920 -> 1 CTA/SM.
// ---------------------------------------------------------------------------
#define N_B1  0         // bn1 512
#define N_B2  512       // bn2 512
#define N_W1B 1024      // 128 x 272 = 34816
#define N_W2H 35840
#define N_W2L 70656
#define N_XA  105472    // 128 x 272 (agg bf16)
#define N_THI 140288
#define N_TLO 175104
#define SM_NODE_TOTAL 209920

__global__ __launch_bounds__(512, 1) void k_node(
    const float* __restrict__ Wn1, const float* __restrict__ bn1,
    const float* __restrict__ Wn2, const float* __restrict__ bn2,
    float* __restrict__ out)
{
    extern __shared__ __align__(16) char sm[];
    float* bn1s = (float*)(sm + N_B1);
    float* bn2s = (float*)(sm + N_B2);
    const uint32_t sbase = smem_u32(sm);
    const int tid = threadIdx.x, wid = tid >> 5, lane = tid & 31;
    const int wr = wid & 3, wc = wid >> 2;
    const int g = lane >> 2, q = lane & 3;

    // Wn1_bot (rows 128..255) single bf16; Wn2 split hi/lo
    for (int i = tid; i < 128 * 128; i += 512) {
        int k = i >> 7, n = i & 127;
        *(__nv_bfloat16*)(sm + N_W1B + k * WPITCH + n * 2) =
            __float2bfloat16(Wn1[(128 + k) * 128 + n]);
        float w2 = Wn2[i];
        __nv_bfloat16 whi = __float2bfloat16(w2);
        *(__nv_bfloat16*)(sm + N_W2H + k * WPITCH + n * 2) = whi;
        *(__nv_bfloat16*)(sm + N_W2L + k * WPITCH + n * 2) =
            __float2bfloat16(w2 - __bfloat162float(whi));
    }
    if (tid < 128) { bn1s[tid] = bn1[tid]; bn2s[tid] = bn2[tid]; }
    __syncthreads();

    const float4* a4 = (const float4*)g_agg;
    float d[2][4][4];
    const int numTiles = (V_N + 127) / 128;   // 391

    for (int tile = blockIdx.x; tile < numTiles; tile += gridDim.x) {
        const int n0 = tile * 128;
        __syncthreads();
        // stage agg bf16
        for (int i = tid; i < 128 * 32; i += 512) {
            int r = i >> 5, j = i & 31;
            int node = n0 + r;
            float4 v = (node < V_N) ? a4[(size_t)node * 32 + j]
                                    : make_float4(0.f, 0.f, 0.f, 0.f);
            uint2 u; u.x = pack2(v.x, v.y); u.y = pack2(v.z, v.w);
            *(uint2*)(sm + N_XA + r * WPITCH + j * 8) = u;
        }
        __syncthreads();

        // GEMM A: agg @ Wn1_bot
        zero_d(d);
        gemm_tile<8, WPITCH>(sbase + N_XA, sbase + N_W1B, wr, wc, lane, d);

        // T = relu(d + R + bn1), split -> Thi/Tlo
#pragma unroll
        for (int mi = 0; mi < 2; mi++) {
            const int rA = wr * 32 + mi * 16 + g;
            const int nodeA = n0 + rA, nodeB = nodeA + 8;
#pragma unroll
            for (int ni = 0; ni < 4; ni++) {
                const int c = wc * 32 + ni * 8 + 2 * q;
                float2 bb = *(const float2*)&bn1s[c];
                float2 r0 = (nodeA < V_N) ? *(const float2*)&g_R[(size_t)nodeA * 128 + c]
                                          : make_float2(0.f, 0.f);
                float2 r1 = (nodeB < V_N) ? *(const float2*)&g_R[(size_t)nodeB * 128 + c]
                                          : make_float2(0.f, 0.f);
                float t0 = fmaxf(d[mi][ni][0] + r0.x + bb.x, 0.f);
                float t1 = fmaxf(d[mi][ni][1] + r0.y + bb.y, 0.f);
                float t2 = fmaxf(d[mi][ni][2] + r1.x + bb.x, 0.f);
                float t3 = fmaxf(d[mi][ni][3] + r1.y + bb.y, 0.f);
                __nv_bfloat16 h0 = __float2bfloat16(t0), h1 = __float2bfloat16(t1);
                __nv_bfloat16 h2 = __float2bfloat16(t2), h3 = __float2bfloat16(t3);
                *(uint32_t*)(sm + N_THI + rA * WPITCH + c * 2) =
                    pack2(__bfloat162float(h0), __bfloat162float(h1));
                *(uint32_t*)(sm + N_THI + (rA + 8) * WPITCH + c * 2) =
                    pack2(__bfloat162float(h2), __bfloat162float(h3));
                *(uint32_t*)(sm + N_TLO + rA * WPITCH + c * 2) =
                    pack2(t0 - __bfloat162float(h0), t1 - __bfloat162float(h1));
                *(uint32_t*)(sm + N_TLO + (rA + 8) * WPITCH + c * 2) =
                    pack2(t2 - __bfloat162float(h2), t3 - __bfloat162float(h3));
            }
        }
        __syncthreads();

        // GEMM B: out = Thi@W2hi + Thi@W2lo + Tlo@W2hi + bn2
        zero_d(d);
        gemm_tile<8, WPITCH>(sbase + N_THI, sbase + N_W2H, wr, wc, lane, d);
        gemm_tile<8, WPITCH>(sbase + N_THI, sbase + N_W2L, wr, wc, lane, d);
        gemm_tile<8, WPITCH>(sbase + N_TLO, sbase + N_W2H, wr, wc, lane, d);

#pragma unroll
        for (int mi = 0; mi < 2; mi++) {
            const int rA = wr * 32 + mi * 16 + g;
            const int nodeA = n0 + rA, nodeB = nodeA + 8;
#pragma unroll
            for (int ni = 0; ni < 4; ni++) {
                const int c = wc * 32 + ni * 8 + 2 * q;
                float2 bb = *(const float2*)&bn2s[c];
                if (nodeA < V_N)
                    *(float2*)&out[(size_t)nodeA * 128 + c] =
                        make_float2(d[mi][ni][0] + bb.x, d[mi][ni][1] + bb.y);
                if (nodeB < V_N)
                    *(float2*)&out[(size_t)nodeB * 128 + c] =
                        make_float2(d[mi][ni][2] + bb.x, d[mi][ni][3] + bb.y);
            }
        }
    }
}

// ---------------------------------------------------------------------------
extern "C" void kernel_launch(void* const* d_in, const int* in_sizes, int n_in,
                              void* d_out, int out_size) {
    const float* h   = (const float*)d_in[0];
    const int*   ei  = (const int*)d_in[1];   // int32 (JAX x64 disabled)
    const float* W1  = (const float*)d_in[2];
    const float* b1  = (const float*)d_in[3];
    const float* W2  = (const float*)d_in[4];
    const float* b2  = (const float*)d_in[5];
    const float* W3  = (const float*)d_in[6];
    const float* b3  = (const float*)d_in[7];
    const float* Wn1 = (const float*)d_in[8];
    const float* bn1 = (const float*)d_in[9];
    const float* Wn2 = (const float*)d_in[10];
    const float* bn2 = (const float*)d_in[11];
    float*       out = (float*)d_out;

    cudaFuncSetAttribute(k_pq,   cudaFuncAttributeMaxDynamicSharedMemorySize, SM_PQ_TOTAL);
    cudaFuncSetAttribute(k_r,    cudaFuncAttributeMaxDynamicSharedMemorySize, SM_R_TOTAL);
    cudaFuncSetAttribute(k_edge, cudaFuncAttributeMaxDynamicSharedMemorySize, SM_EDGE_TOTAL);
    cudaFuncSetAttribute(k_node, cudaFuncAttributeMaxDynamicSharedMemorySize, SM_NODE_TOTAL);

    k_zero_agg<<<512, 256>>>();
    k_pq<<<296, 256, SM_PQ_TOTAL>>>(h, W1);
    k_r<<<296, 256, SM_R_TOTAL>>>(h, Wn1);
    k_edge<<<148, 512, SM_EDGE_TOTAL>>>(ei, b1, W2, b2, W3, b3);
    k_node<<<148, 512, SM_NODE_TOTAL>>>(Wn1, bn1, Wn2, bn2, out);
}

// round 9
// speedup vs baseline: 2.3561x; 1.2541x over previous
#include <cuda_runtime.h>
#include <cuda_bf16.h>
#include <cstdint>

// Problem constants (fixed shapes)
#define V_N 50000
#define E_N 800000

// Scratch (static device arrays — no runtime allocation)
__device__ float g_agg[(size_t)V_N * 128];          // scatter accumulator (25.6 MB)
__device__ __nv_bfloat16 g_PQ[(size_t)V_N * 256];   // [P | Q] per node, bf16 (25.6 MB)
__device__ float g_R[(size_t)V_N * 128];            // h @ Wn1_top (near-fp32)

// ============================================================================
// Warp-level MMA helpers (base PTX: ldmatrix sm_75+, mma.sync bf16 sm_80+)
// ============================================================================
__device__ __forceinline__ uint32_t smem_u32(const void* p) {
    uint32_t a;
    asm("{ .reg .u64 t; cvta.to.shared.u64 t, %1; cvt.u32.u64 %0, t; }"
        : "=r"(a) : "l"(p));
    return a;
}
__device__ __forceinline__ void ldsm_x4(uint32_t* r, uint32_t addr) {
    asm volatile("ldmatrix.sync.aligned.m8n8.x4.shared.b16 {%0,%1,%2,%3}, [%4];"
                 : "=r"(r[0]), "=r"(r[1]), "=r"(r[2]), "=r"(r[3]) : "r"(addr));
}
__device__ __forceinline__ void ldsm_x4_t(uint32_t* r, uint32_t addr) {
    asm volatile("ldmatrix.sync.aligned.m8n8.x4.trans.shared.b16 {%0,%1,%2,%3}, [%4];"
                 : "=r"(r[0]), "=r"(r[1]), "=r"(r[2]), "=r"(r[3]) : "r"(addr));
}
__device__ __forceinline__ void mma_bf16(float* d, const uint32_t* a, const uint32_t* b) {
    asm volatile(
        "mma.sync.aligned.m16n8k16.row.col.f32.bf16.bf16.f32 "
        "{%0,%1,%2,%3}, {%4,%5,%6,%7}, {%8,%9}, {%0,%1,%2,%3};"
        : "+f"(d[0]), "+f"(d[1]), "+f"(d[2]), "+f"(d[3])
        : "r"(a[0]), "r"(a[1]), "r"(a[2]), "r"(a[3]), "r"(b[0]), "r"(b[1]));
}
__device__ __forceinline__ uint32_t pack2(float a, float b) {
    __nv_bfloat162 p = __floats2bfloat162_rn(a, b);
    return *(uint32_t*)&p;
}
__device__ __forceinline__ void red_add_v2(float* p, float a, float b) {
    asm volatile("red.global.add.v2.f32 [%0], {%1, %2};"
                 :: "l"(p), "f"(a), "f"(b) : "memory");
}
// relu(bf16x2(p) + bf16x2(q) + bf16x2(b)) computed in fp32, repacked bf16x2
__device__ __forceinline__ uint32_t addrelu2(uint32_t p, uint32_t q, uint32_t b) {
    float2 fp = __bfloat1622float2(*(__nv_bfloat162*)&p);
    float2 fq = __bfloat1622float2(*(__nv_bfloat162*)&q);
    float2 fb = __bfloat1622float2(*(__nv_bfloat162*)&b);
    return pack2(fmaxf(fp.x + fq.x + fb.x, 0.f), fmaxf(fp.y + fq.y + fb.y, 0.f));
}

#define WPITCH 272   // bf16 tile pitch for 128-col matrices
#define BPITCH 528   // bf16 tile pitch for 256-col matrix (k_pq weights)

// Warp-tile GEMM (ACCUMULATES into d; caller zeroes):
template <int NK, int AP>
__device__ __forceinline__ void gemm_tile(uint32_t abase, uint32_t wbase,
                                          int wr, int wc, int lane,
                                          float d[2][4][4]) {
    const int l15 = lane & 15;
    const int kh  = (lane >> 4) << 3;
#pragma unroll
    for (int ks = 0; ks < NK; ks++) {
        uint32_t a[2][4], b[4][2];
#pragma unroll
        for (int mi = 0; mi < 2; mi++) {
            uint32_t addr = abase + (uint32_t)((wr * 32 + mi * 16 + l15) * AP +
                                               (ks * 16 + kh) * 2);
            ldsm_x4(a[mi], addr);
        }
#pragma unroll
        for (int nj = 0; nj < 2; nj++) {
            uint32_t addr = wbase + (uint32_t)((ks * 16 + l15) * WPITCH +
                                               (wc * 32 + nj * 16 + kh) * 2);
            uint32_t t[4];
            ldsm_x4_t(t, addr);
            b[2 * nj][0] = t[0]; b[2 * nj][1] = t[1];
            b[2 * nj + 1][0] = t[2]; b[2 * nj + 1][1] = t[3];
        }
#pragma unroll
        for (int mi = 0; mi < 2; mi++)
#pragma unroll
            for (int ni = 0; ni < 4; ni++)
                mma_bf16(d[mi][ni], a[mi], b[ni]);
    }
}
__device__ __forceinline__ void zero_d(float d[2][4][4]) {
#pragma unroll
    for (int mi = 0; mi < 2; mi++)
#pragma unroll
        for (int ni = 0; ni < 4; ni++)
#pragma unroll
            for (int x = 0; x < 4; x++) d[mi][ni][x] = 0.f;
}

// Epilogue: relu(d + bias) -> bf16 tile at dstbase (pitch P bytes)
template <int P>
__device__ __forceinline__ void epi_relu_bf16(char* dstbase, const float* bias,
                                              float d[2][4][4],
                                              int wr, int wc, int lane) {
    const int g = lane >> 2, q = lane & 3;
#pragma unroll
    for (int mi = 0; mi < 2; mi++) {
        const int rA = wr * 32 + mi * 16 + g;
#pragma unroll
        for (int ni = 0; ni < 4; ni++) {
            const int c = wc * 32 + ni * 8 + 2 * q;
            float2 bb = *(const float2*)&bias[c];
            float v0 = fmaxf(d[mi][ni][0] + bb.x, 0.f);
            float v1 = fmaxf(d[mi][ni][1] + bb.y, 0.f);
            float v2 = fmaxf(d[mi][ni][2] + bb.x, 0.f);
            float v3 = fmaxf(d[mi][ni][3] + bb.y, 0.f);
            *(uint32_t*)(dstbase + rA * P + c * 2)       = pack2(v0, v1);
            *(uint32_t*)(dstbase + (rA + 8) * P + c * 2) = pack2(v2, v3);
        }
    }
}

// ---------------------------------------------------------------------------
__global__ void k_zero_agg() {
    const int n4 = V_N * 128 / 4;
    float4 z = make_float4(0.f, 0.f, 0.f, 0.f);
    for (int i = blockIdx.x * blockDim.x + threadIdx.x; i < n4;
         i += gridDim.x * blockDim.x)
        ((float4*)g_agg)[i] = z;
}

// ---------------------------------------------------------------------------
// k_pq: g_PQ[v] = [h[v]@W1_top | h[v]@W1_bot] in bf16.
// ---------------------------------------------------------------------------
#define PQ_W 0                 // 128 x 528B = 67584
#define PQ_H 67584             // 64 x 272B = 17408
#define SM_PQ_TOTAL 84992

__global__ __launch_bounds__(256, 2) void k_pq(
    const float* __restrict__ h, const float* __restrict__ W1)
{
    extern __shared__ __align__(16) char sm[];
    const uint32_t sbase = smem_u32(sm);
    const uint32_t sW = sbase + PQ_W, sH = sbase + PQ_H;
    const int tid = threadIdx.x, wid = tid >> 5, lane = tid & 31;
    const int wr = wid & 1, wc = wid >> 1;
    const int l15 = lane & 15, kh = (lane >> 4) << 3;
    const int g = lane >> 2, q = lane & 3;

    for (int i = tid; i < 128 * 256; i += 256) {
        int k = i >> 8, n = i & 255;
        float w = (n < 128) ? W1[k * 128 + n] : W1[(128 + k) * 128 + (n - 128)];
        *(__nv_bfloat16*)(sm + PQ_W + k * BPITCH + n * 2) = __float2bfloat16(w);
    }
    __syncthreads();

    const float4* h4 = (const float4*)h;
    const int numTiles = (V_N + 63) / 64;   // 782

    for (int tile = blockIdx.x; tile < numTiles; tile += gridDim.x) {
        const int n0 = tile * 64;
        __syncthreads();
        for (int i = tid; i < 64 * 32; i += 256) {
            int r = i >> 5, j = i & 31;
            int node = n0 + r;
            float4 v = (node < V_N) ? h4[(size_t)node * 32 + j]
                                    : make_float4(0.f, 0.f, 0.f, 0.f);
            uint2 u; u.x = pack2(v.x, v.y); u.y = pack2(v.z, v.w);
            *(uint2*)(sm + PQ_H + r * WPITCH + j * 8) = u;
        }
        __syncthreads();

        float d[2][8][4];
#pragma unroll
        for (int mi = 0; mi < 2; mi++)
#pragma unroll
            for (int ni = 0; ni < 8; ni++)
#pragma unroll
                for (int x = 0; x < 4; x++) d[mi][ni][x] = 0.f;

#pragma unroll
        for (int ks = 0; ks < 8; ks++) {
            uint32_t a[2][4], b[8][2];
#pragma unroll
            for (int mi = 0; mi < 2; mi++) {
                uint32_t addr = sH + (uint32_t)((wr * 32 + mi * 16 + l15) * WPITCH +
                                                (ks * 16 + kh) * 2);
                ldsm_x4(a[mi], addr);
            }
#pragma unroll
            for (int nj = 0; nj < 4; nj++) {
                uint32_t addr = sW + (uint32_t)((ks * 16 + l15) * BPITCH +
                                                (wc * 64 + nj * 16 + kh) * 2);
                uint32_t t[4];
                ldsm_x4_t(t, addr);
                b[2 * nj][0] = t[0]; b[2 * nj][1] = t[1];
                b[2 * nj + 1][0] = t[2]; b[2 * nj + 1][1] = t[3];
            }
#pragma unroll
            for (int mi = 0; mi < 2; mi++)
#pragma unroll
                for (int ni = 0; ni < 8; ni++)
                    mma_bf16(d[mi][ni], a[mi], b[ni]);
        }

#pragma unroll
        for (int mi = 0; mi < 2; mi++) {
            const int rA = wr * 32 + mi * 16 + g;
            const int nodeA = n0 + rA, nodeB = nodeA + 8;
#pragma unroll
            for (int ni = 0; ni < 8; ni++) {
                const int c = wc * 64 + ni * 8 + 2 * q;
                if (nodeA < V_N)
                    *(uint32_t*)&g_PQ[(size_t)nodeA * 256 + c] =
                        pack2(d[mi][ni][0], d[mi][ni][1]);
                if (nodeB < V_N)
                    *(uint32_t*)&g_PQ[(size_t)nodeB * 256 + c] =
                        pack2(d[mi][ni][2], d[mi][ni][3]);
            }
        }
    }
}

// ---------------------------------------------------------------------------
// k_r: R = h @ Wn1_top in 3-term split-bf16 (near-fp32 accuracy).
// ---------------------------------------------------------------------------
#define R_WH 0
#define R_WL 34816
#define R_HH 69632
#define R_HL 87040
#define SM_R_TOTAL 104448

__global__ __launch_bounds__(256, 2) void k_r(
    const float* __restrict__ h, const float* __restrict__ Wn1)
{
    extern __shared__ __align__(16) char sm[];
    const uint32_t sbase = smem_u32(sm);
    const int tid = threadIdx.x, wid = tid >> 5, lane = tid & 31;
    const int wr = wid & 1, wc = wid >> 1;
    const int g = lane >> 2, q = lane & 3;

    for (int i = tid; i < 128 * 128; i += 256) {
        int k = i >> 7, n = i & 127;
        float w = Wn1[k * 128 + n];
        __nv_bfloat16 whi = __float2bfloat16(w);
        float wlo = w - __bfloat162float(whi);
        *(__nv_bfloat16*)(sm + R_WH + k * WPITCH + n * 2) = whi;
        *(__nv_bfloat16*)(sm + R_WL + k * WPITCH + n * 2) = __float2bfloat16(wlo);
    }
    __syncthreads();

    const float4* h4 = (const float4*)h;
    const int numTiles = (V_N + 63) / 64;

    for (int tile = blockIdx.x; tile < numTiles; tile += gridDim.x) {
        const int n0 = tile * 64;
        __syncthreads();
        for (int i = tid; i < 64 * 32; i += 256) {
            int r = i >> 5, j = i & 31;
            int node = n0 + r;
            float4 v = (node < V_N) ? h4[(size_t)node * 32 + j]
                                    : make_float4(0.f, 0.f, 0.f, 0.f);
            __nv_bfloat16 h0 = __float2bfloat16(v.x), h1 = __float2bfloat16(v.y);
            __nv_bfloat16 h2 = __float2bfloat16(v.z), h3 = __float2bfloat16(v.w);
            uint2 uh, ul;
            uh.x = pack2(__bfloat162float(h0), __bfloat162float(h1));
            uh.y = pack2(__bfloat162float(h2), __bfloat162float(h3));
            ul.x = pack2(v.x - __bfloat162float(h0), v.y - __bfloat162float(h1));
            ul.y = pack2(v.z - __bfloat162float(h2), v.w - __bfloat162float(h3));
            *(uint2*)(sm + R_HH + r * WPITCH + j * 8) = uh;
            *(uint2*)(sm + R_HL + r * WPITCH + j * 8) = ul;
        }
        __syncthreads();

        float d[2][4][4];
        zero_d(d);
        gemm_tile<8, WPITCH>(sbase + R_HH, sbase + R_WH, wr, wc, lane, d);
        gemm_tile<8, WPITCH>(sbase + R_HH, sbase + R_WL, wr, wc, lane, d);
        gemm_tile<8, WPITCH>(sbase + R_HL, sbase + R_WH, wr, wc, lane, d);

#pragma unroll
        for (int mi = 0; mi < 2; mi++) {
            const int rA = wr * 32 + mi * 16 + g;
            const int nodeA = n0 + rA, nodeB = nodeA + 8;
#pragma unroll
            for (int ni = 0; ni < 4; ni++) {
                const int c = wc * 32 + ni * 8 + 2 * q;
                if (nodeA < V_N)
                    *(float2*)&g_R[(size_t)nodeA * 128 + c] =
                        make_float2(d[mi][ni][0], d[mi][ni][1]);
                if (nodeB < V_N)
                    *(float2*)&g_R[(size_t)nodeB * 128 + c] =
                        make_float2(d[mi][ni][2], d[mi][ni][3]);
            }
        }
    }
}

// ---------------------------------------------------------------------------
// k_edge (software-pipelined): 128-edge tiles, 512 threads, 2 syncs/tile.
//   P1 (fused with prev tile): scatter(t-1) + gather A2(t) into alt buffer
//   P2: GEMM2 + epi A3;  P3: GEMM3
// Indices read straight from ei (L1-hot) — no smem idx staging.
// ---------------------------------------------------------------------------
#define SM_B1BF 0        // 128 bf16 = 256B
#define SM_B2S  256      // 128 f32 = 512B
#define SM_B3S  768      // 512B
#define SM_W2   1280     // 128 x 272 = 34816
#define SM_W3   36096
#define SM_A2A  70912
#define SM_A2B  105728
#define SM_A3   140544
#define SM_EDGE_TOTAL 175360

__global__ __launch_bounds__(512, 1) void k_edge(
    const int* __restrict__ ei,
    const float* __restrict__ b1,
    const float* __restrict__ W2, const float* __restrict__ b2,
    const float* __restrict__ W3, const float* __restrict__ b3)
{
    extern __shared__ __align__(16) char sm[];
    float* b2s = (float*)(sm + SM_B2S);
    float* b3s = (float*)(sm + SM_B3S);
    const uint32_t sbase = smem_u32(sm);
    const uint32_t sW2 = sbase + SM_W2, sW3 = sbase + SM_W3;
    const uint32_t sA3 = sbase + SM_A3;

    const int tid = threadIdx.x, wid = tid >> 5, lane = tid & 31;
    const int wr = wid & 3, wc = wid >> 2;
    const int g = lane >> 2, q = lane & 3;

    for (int i = tid; i < 128 * 128; i += 512) {
        int k = i >> 7, n = i & 127;
        *(__nv_bfloat16*)(sm + SM_W2 + k * WPITCH + n * 2) = __float2bfloat16(W2[i]);
        *(__nv_bfloat16*)(sm + SM_W3 + k * WPITCH + n * 2) = __float2bfloat16(W3[i]);
    }
    if (tid < 128) {
        b2s[tid] = b2[tid];
        b3s[tid] = b3[tid];
        *(__nv_bfloat16*)(sm + SM_B1BF + tid * 2) = __float2bfloat16(b1[tid]);
    }
    __syncthreads();

    // per-thread gather constants: this thread always handles col-group jg
    const int jg = tid & 15;                  // 8-col (16B) group
    const int r0 = tid >> 4;                  // base row (0..31)
    const uint4 Bv = *(const uint4*)(sm + SM_B1BF + jg * 16);

    const int numTiles = E_N / 128;   // 6250
    float d[2][4][4];
    int buf = 0;

    // Prologue: gather first tile into buffer A
    int tile = blockIdx.x;
    if (tile < numTiles) {
        const int e0 = tile * 128;
        char* a2p = sm + SM_A2A;
#pragma unroll
        for (int k = 0; k < 4; k++) {
            int r = r0 + 32 * k;
            int s = ei[e0 + r], t = ei[E_N + e0 + r];
            uint4 P = *(const uint4*)&g_PQ[(size_t)s * 256 + jg * 8];
            uint4 Q = *(const uint4*)&g_PQ[(size_t)t * 256 + 128 + jg * 8];
            uint4 o;
            o.x = addrelu2(P.x, Q.x, Bv.x);
            o.y = addrelu2(P.y, Q.y, Bv.y);
            o.z = addrelu2(P.z, Q.z, Bv.z);
            o.w = addrelu2(P.w, Q.w, Bv.w);
            *(uint4*)(a2p + r * WPITCH + jg * 16) = o;
        }
    }

    for (; tile < numTiles; tile += gridDim.x) {
        const int e0 = tile * 128;
        __syncthreads();   // A2[buf] ready; A3 free (prev GEMM3 done)

        // ---- P2: GEMM2 + epi -> A3 ----
        zero_d(d);
        gemm_tile<8, WPITCH>(sbase + (buf ? SM_A2B : SM_A2A), sW2, wr, wc, lane, d);
        epi_relu_bf16<WPITCH>(sm + SM_A3, b2s, d, wr, wc, lane);
        __syncthreads();   // A3 ready

        // ---- P3: GEMM3 ----
        zero_d(d);
        gemm_tile<8, WPITCH>(sA3, sW3, wr, wc, lane, d);

        // ---- P1 (next iter overlap): scatter(t), gather(t+gridDim) ----
        {
            const int rA = wr * 32 + g;
#pragma unroll
            for (int mi = 0; mi < 2; mi++) {
                const int rr = rA + mi * 16;
                const int d0 = ei[E_N + e0 + rr], d1 = ei[E_N + e0 + rr + 8];
#pragma unroll
                for (int ni = 0; ni < 4; ni++) {
                    const int c = wc * 32 + ni * 8 + 2 * q;
                    float2 bb = *(const float2*)&b3s[c];
                    red_add_v2(g_agg + (size_t)d0 * 128 + c,
                               d[mi][ni][0] + bb.x, d[mi][ni][1] + bb.y);
                    red_add_v2(g_agg + (size_t)d1 * 128 + c,
                               d[mi][ni][2] + bb.x, d[mi][ni][3] + bb.y);
                }
            }
        }
        const int nt = tile + gridDim.x;
        if (nt < numTiles) {
            const int ne0 = nt * 128;
            char* a2p = sm + (buf ? SM_A2A : SM_A2B);   // alternate buffer
#pragma unroll
            for (int k = 0; k < 4; k++) {
                int r = r0 + 32 * k;
                int s = ei[ne0 + r], t = ei[E_N + ne0 + r];
                uint4 P = *(const uint4*)&g_PQ[(size_t)s * 256 + jg * 8];
                uint4 Q = *(const uint4*)&g_PQ[(size_t)t * 256 + 128 + jg * 8];
                uint4 o;
                o.x = addrelu2(P.x, Q.x, Bv.x);
                o.y = addrelu2(P.y, Q.y, Bv.y);
                o.z = addrelu2(P.z, Q.z, Bv.z);
                o.w = addrelu2(P.w, Q.w, Bv.w);
                *(uint4*)(a2p + r * WPITCH + jg * 16) = o;
            }
        }
        buf ^= 1;
    }
}

// ---------------------------------------------------------------------------
// k_node (tensor): T = relu(R + agg@Wn1_bot + bn1); out = T@Wn2 (3-term split).
// ---------------------------------------------------------------------------
#define N_B1  0
#define N_B2  512
#define N_W1B 1024
#define N_W2H 35840
#define N_W2L 70656
#define N_XA  105472
#define N_THI 140288
#define N_TLO 175104
#define SM_NODE_TOTAL 209920

__global__ __launch_bounds__(512, 1) void k_node(
    const float* __restrict__ Wn1, const float* __restrict__ bn1,
    const float* __restrict__ Wn2, const float* __restrict__ bn2,
    float* __restrict__ out)
{
    extern __shared__ __align__(16) char sm[];
    float* bn1s = (float*)(sm + N_B1);
    float* bn2s = (float*)(sm + N_B2);
    const uint32_t sbase = smem_u32(sm);
    const int tid = threadIdx.x, wid = tid >> 5, lane = tid & 31;
    const int wr = wid & 3, wc = wid >> 2;
    const int g = lane >> 2, q = lane & 3;

    for (int i = tid; i < 128 * 128; i += 512) {
        int k = i >> 7, n = i & 127;
        *(__nv_bfloat16*)(sm + N_W1B + k * WPITCH + n * 2) =
            __float2bfloat16(Wn1[(128 + k) * 128 + n]);
        float w2 = Wn2[i];
        __nv_bfloat16 whi = __float2bfloat16(w2);
        *(__nv_bfloat16*)(sm + N_W2H + k * WPITCH + n * 2) = whi;
        *(__nv_bfloat16*)(sm + N_W2L + k * WPITCH + n * 2) =
            __float2bfloat16(w2 - __bfloat162float(whi));
    }
    if (tid < 128) { bn1s[tid] = bn1[tid]; bn2s[tid] = bn2[tid]; }
    __syncthreads();

    const float4* a4 = (const float4*)g_agg;
    float d[2][4][4];
    const int numTiles = (V_N + 127) / 128;   // 391

    for (int tile = blockIdx.x; tile < numTiles; tile += gridDim.x) {
        const int n0 = tile * 128;
        __syncthreads();
        for (int i = tid; i < 128 * 32; i += 512) {
            int r = i >> 5, j = i & 31;
            int node = n0 + r;
            float4 v = (node < V_N) ? a4[(size_t)node * 32 + j]
                                    : make_float4(0.f, 0.f, 0.f, 0.f);
            uint2 u; u.x = pack2(v.x, v.y); u.y = pack2(v.z, v.w);
            *(uint2*)(sm + N_XA + r * WPITCH + j * 8) = u;
        }
        __syncthreads();

        zero_d(d);
        gemm_tile<8, WPITCH>(sbase + N_XA, sbase + N_W1B, wr, wc, lane, d);

#pragma unroll
        for (int mi = 0; mi < 2; mi++) {
            const int rA = wr * 32 + mi * 16 + g;
            const int nodeA = n0 + rA, nodeB = nodeA + 8;
#pragma unroll
            for (int ni = 0; ni < 4; ni++) {
                const int c = wc * 32 + ni * 8 + 2 * q;
                float2 bb = *(const float2*)&bn1s[c];
                float2 r0 = (nodeA < V_N) ? *(const float2*)&g_R[(size_t)nodeA * 128 + c]
                                          : make_float2(0.f, 0.f);
                float2 r1 = (nodeB < V_N) ? *(const float2*)&g_R[(size_t)nodeB * 128 + c]
                                          : make_float2(0.f, 0.f);
                float t0 = fmaxf(d[mi][ni][0] + r0.x + bb.x, 0.f);
                float t1 = fmaxf(d[mi][ni][1] + r0.y + bb.y, 0.f);
                float t2 = fmaxf(d[mi][ni][2] + r1.x + bb.x, 0.f);
                float t3 = fmaxf(d[mi][ni][3] + r1.y + bb.y, 0.f);
                __nv_bfloat16 h0 = __float2bfloat16(t0), h1 = __float2bfloat16(t1);
                __nv_bfloat16 h2 = __float2bfloat16(t2), h3 = __float2bfloat16(t3);
                *(uint32_t*)(sm + N_THI + rA * WPITCH + c * 2) =
                    pack2(__bfloat162float(h0), __bfloat162float(h1));
                *(uint32_t*)(sm + N_THI + (rA + 8) * WPITCH + c * 2) =
                    pack2(__bfloat162float(h2), __bfloat162float(h3));
                *(uint32_t*)(sm + N_TLO + rA * WPITCH + c * 2) =
                    pack2(t0 - __bfloat162float(h0), t1 - __bfloat162float(h1));
                *(uint32_t*)(sm + N_TLO + (rA + 8) * WPITCH + c * 2) =
                    pack2(t2 - __bfloat162float(h2), t3 - __bfloat162float(h3));
            }
        }
        __syncthreads();

        zero_d(d);
        gemm_tile<8, WPITCH>(sbase + N_THI, sbase + N_W2H, wr, wc, lane, d);
        gemm_tile<8, WPITCH>(sbase + N_THI, sbase + N_W2L, wr, wc, lane, d);
        gemm_tile<8, WPITCH>(sbase + N_TLO, sbase + N_W2H, wr, wc, lane, d);

#pragma unroll
        for (int mi = 0; mi < 2; mi++) {
            const int rA = wr * 32 + mi * 16 + g;
            const int nodeA = n0 + rA, nodeB = nodeA + 8;
#pragma unroll
            for (int ni = 0; ni < 4; ni++) {
                const int c = wc * 32 + ni * 8 + 2 * q;
                float2 bb = *(const float2*)&bn2s[c];
                if (nodeA < V_N)
                    *(float2*)&out[(size_t)nodeA * 128 + c] =
                        make_float2(d[mi][ni][0] + bb.x, d[mi][ni][1] + bb.y);
                if (nodeB < V_N)
                    *(float2*)&out[(size_t)nodeB * 128 + c] =
                        make_float2(d[mi][ni][2] + bb.x, d[mi][ni][3] + bb.y);
            }
        }
    }
}

// ---------------------------------------------------------------------------
extern "C" void kernel_launch(void* const* d_in, const int* in_sizes, int n_in,
                              void* d_out, int out_size) {
    const float* h   = (const float*)d_in[0];
    const int*   ei  = (const int*)d_in[1];   // int32 (JAX x64 disabled)
    const float* W1  = (const float*)d_in[2];
    const float* b1  = (const float*)d_in[3];
    const float* W2  = (const float*)d_in[4];
    const float* b2  = (const float*)d_in[5];
    const float* W3  = (const float*)d_in[6];
    const float* b3  = (const float*)d_in[7];
    const float* Wn1 = (const float*)d_in[8];
    const float* bn1 = (const float*)d_in[9];
    const float* Wn2 = (const float*)d_in[10];
    const float* bn2 = (const float*)d_in[11];
    float*       out = (float*)d_out;

    cudaFuncSetAttribute(k_pq,   cudaFuncAttributeMaxDynamicSharedMemorySize, SM_PQ_TOTAL);
    cudaFuncSetAttribute(k_r,    cudaFuncAttributeMaxDynamicSharedMemorySize, SM_R_TOTAL);
    cudaFuncSetAttribute(k_edge, cudaFuncAttributeMaxDynamicSharedMemorySize, SM_EDGE_TOTAL);
    cudaFuncSetAttribute(k_node, cudaFuncAttributeMaxDynamicSharedMemorySize, SM_NODE_TOTAL);

    k_zero_agg<<<512, 256>>>();
    k_pq<<<296, 256, SM_PQ_TOTAL>>>(h, W1);
    k_r<<<296, 256, SM_R_TOTAL>>>(h, Wn1);
    k_edge<<<148, 512, SM_EDGE_TOTAL>>>(ei, b1, W2, b2, W3, b3);
    k_node<<<148, 512, SM_NODE_TOTAL>>>(Wn1, bn1, Wn2, bn2, out);
}

// round 10
// speedup vs baseline: 3.1161x; 1.3226x over previous
#include <cuda_runtime.h>
#include <cuda_bf16.h>
#include <cuda_fp16.h>
#include <cstdint>

// Problem constants (fixed shapes)
#define V_N 50000
#define E_N 800000

// Scratch (static device arrays — no runtime allocation)
__device__ __half g_S[(size_t)V_N * 128];           // Σ A3 per node, fp16 (12.8 MB)
__device__ int    g_deg[V_N];                       // in-degree
__device__ __nv_bfloat16 g_PQ[(size_t)V_N * 256];   // [P | Q] per node, bf16 (25.6 MB)
__device__ float  g_R[(size_t)V_N * 128];           // h @ Wn1_top (near-fp32)
__device__ __half g_W3n[128 * 128];                 // W3 @ Wn1_bot, fp16
__device__ float  g_bn3[128];                       // b3 @ Wn1_bot

// ============================================================================
// Warp-level MMA helpers (base PTX: ldmatrix sm_75+, mma.sync sm_80+)
// ============================================================================
__device__ __forceinline__ uint32_t smem_u32(const void* p) {
    uint32_t a;
    asm("{ .reg .u64 t; cvta.to.shared.u64 t, %1; cvt.u32.u64 %0, t; }"
        : "=r"(a) : "l"(p));
    return a;
}
__device__ __forceinline__ void ldsm_x4(uint32_t* r, uint32_t addr) {
    asm volatile("ldmatrix.sync.aligned.m8n8.x4.shared.b16 {%0,%1,%2,%3}, [%4];"
                 : "=r"(r[0]), "=r"(r[1]), "=r"(r[2]), "=r"(r[3]) : "r"(addr));
}
__device__ __forceinline__ void ldsm_x4_t(uint32_t* r, uint32_t addr) {
    asm volatile("ldmatrix.sync.aligned.m8n8.x4.trans.shared.b16 {%0,%1,%2,%3}, [%4];"
                 : "=r"(r[0]), "=r"(r[1]), "=r"(r[2]), "=r"(r[3]) : "r"(addr));
}
__device__ __forceinline__ void mma_bf16(float* d, const uint32_t* a, const uint32_t* b) {
    asm volatile(
        "mma.sync.aligned.m16n8k16.row.col.f32.bf16.bf16.f32 "
        "{%0,%1,%2,%3}, {%4,%5,%6,%7}, {%8,%9}, {%0,%1,%2,%3};"
        : "+f"(d[0]), "+f"(d[1]), "+f"(d[2]), "+f"(d[3])
        : "r"(a[0]), "r"(a[1]), "r"(a[2]), "r"(a[3]), "r"(b[0]), "r"(b[1]));
}
__device__ __forceinline__ void mma_f16(float* d, const uint32_t* a, const uint32_t* b) {
    asm volatile(
        "mma.sync.aligned.m16n8k16.row.col.f32.f16.f16.f32 "
        "{%0,%1,%2,%3}, {%4,%5,%6,%7}, {%8,%9}, {%0,%1,%2,%3};"
        : "+f"(d[0]), "+f"(d[1]), "+f"(d[2]), "+f"(d[3])
        : "r"(a[0]), "r"(a[1]), "r"(a[2]), "r"(a[3]), "r"(b[0]), "r"(b[1]));
}
__device__ __forceinline__ uint32_t pack2(float a, float b) {
    __nv_bfloat162 p = __floats2bfloat162_rn(a, b);
    return *(uint32_t*)&p;
}
__device__ __forceinline__ void red_add_h2(__half* p, uint32_t v) {
    asm volatile("red.global.add.noftz.f16x2 [%0], %1;"
                 :: "l"(p), "r"(v) : "memory");
}
// relu(bf16x2(p) + bf16x2(q) + bf16x2(b)) in fp32, repacked bf16x2
__device__ __forceinline__ uint32_t addrelu2(uint32_t p, uint32_t q, uint32_t b) {
    float2 fp = __bfloat1622float2(*(__nv_bfloat162*)&p);
    float2 fq = __bfloat1622float2(*(__nv_bfloat162*)&q);
    float2 fb = __bfloat1622float2(*(__nv_bfloat162*)&b);
    return pack2(fmaxf(fp.x + fq.x + fb.x, 0.f), fmaxf(fp.y + fq.y + fb.y, 0.f));
}

#define WPITCH 272   // b16 tile pitch for 128-col matrices
#define BPITCH 528   // b16 tile pitch for 256-col matrix (k_pq weights)

// Warp-tile GEMM (ACCUMULATES into d; caller zeroes). F16=0 -> bf16 mma.
template <int NK, int AP, int F16>
__device__ __forceinline__ void gemm_tile(uint32_t abase, uint32_t wbase,
                                          int wr, int wc, int lane,
                                          float d[2][4][4]) {
    const int l15 = lane & 15;
    const int kh  = (lane >> 4) << 3;
#pragma unroll
    for (int ks = 0; ks < NK; ks++) {
        uint32_t a[2][4], b[4][2];
#pragma unroll
        for (int mi = 0; mi < 2; mi++) {
            uint32_t addr = abase + (uint32_t)((wr * 32 + mi * 16 + l15) * AP +
                                               (ks * 16 + kh) * 2);
            ldsm_x4(a[mi], addr);
        }
#pragma unroll
        for (int nj = 0; nj < 2; nj++) {
            uint32_t addr = wbase + (uint32_t)((ks * 16 + l15) * WPITCH +
                                               (wc * 32 + nj * 16 + kh) * 2);
            uint32_t t[4];
            ldsm_x4_t(t, addr);
            b[2 * nj][0] = t[0]; b[2 * nj][1] = t[1];
            b[2 * nj + 1][0] = t[2]; b[2 * nj + 1][1] = t[3];
        }
#pragma unroll
        for (int mi = 0; mi < 2; mi++)
#pragma unroll
            for (int ni = 0; ni < 4; ni++) {
                if (F16) mma_f16(d[mi][ni], a[mi], b[ni]);
                else     mma_bf16(d[mi][ni], a[mi], b[ni]);
            }
    }
}
__device__ __forceinline__ void zero_d(float d[2][4][4]) {
#pragma unroll
    for (int mi = 0; mi < 2; mi++)
#pragma unroll
        for (int ni = 0; ni < 4; ni++)
#pragma unroll
            for (int x = 0; x < 4; x++) d[mi][ni][x] = 0.f;
}

// ---------------------------------------------------------------------------
// k_zero: zero g_S and g_deg
// ---------------------------------------------------------------------------
__global__ void k_zero() {
    const uint4 z = make_uint4(0, 0, 0, 0);
    const int nS = V_N * 128 / 8;   // uint4 count over fp16 S
    for (int i = blockIdx.x * blockDim.x + threadIdx.x; i < nS;
         i += gridDim.x * blockDim.x)
        ((uint4*)g_S)[i] = z;
    const int nD = V_N / 4;
    for (int i = blockIdx.x * blockDim.x + threadIdx.x; i < nD;
         i += gridDim.x * blockDim.x)
        ((uint4*)g_deg)[i] = z;
}

// k_deg: in-degree histogram
__global__ void k_deg(const int* __restrict__ ei) {
    for (int i = blockIdx.x * blockDim.x + threadIdx.x; i < E_N;
         i += gridDim.x * blockDim.x)
        atomicAdd(&g_deg[ei[E_N + i]], 1);
}

// k_w3n: W3n = W3 @ Wn1_bot (fp32 -> fp16), bn3 = b3 @ Wn1_bot (fp32)
__global__ void k_w3n(const float* __restrict__ W3, const float* __restrict__ b3,
                      const float* __restrict__ Wn1) {
    const int n = threadIdx.x, k = blockIdx.x;
    float s = 0.f;
    for (int j = 0; j < 128; j++)
        s += W3[k * 128 + j] * Wn1[(128 + j) * 128 + n];
    g_W3n[k * 128 + n] = __float2half(s);
    if (k == 0) {
        float s2 = 0.f;
        for (int j = 0; j < 128; j++)
            s2 += b3[j] * Wn1[(128 + j) * 128 + n];
        g_bn3[n] = s2;
    }
}

// ---------------------------------------------------------------------------
// k_pq: g_PQ[v] = [h[v]@W1_top | h[v]@W1_bot] in bf16.
// ---------------------------------------------------------------------------
#define PQ_W 0                 // 128 x 528B = 67584
#define PQ_H 67584             // 64 x 272B = 17408
#define SM_PQ_TOTAL 84992

__global__ __launch_bounds__(256, 2) void k_pq(
    const float* __restrict__ h, const float* __restrict__ W1)
{
    extern __shared__ __align__(16) char sm[];
    const uint32_t sbase = smem_u32(sm);
    const uint32_t sW = sbase + PQ_W, sH = sbase + PQ_H;
    const int tid = threadIdx.x, wid = tid >> 5, lane = tid & 31;
    const int wr = wid & 1, wc = wid >> 1;
    const int l15 = lane & 15, kh = (lane >> 4) << 3;
    const int g = lane >> 2, q = lane & 3;

    for (int i = tid; i < 128 * 256; i += 256) {
        int k = i >> 8, n = i & 255;
        float w = (n < 128) ? W1[k * 128 + n] : W1[(128 + k) * 128 + (n - 128)];
        *(__nv_bfloat16*)(sm + PQ_W + k * BPITCH + n * 2) = __float2bfloat16(w);
    }
    __syncthreads();

    const float4* h4 = (const float4*)h;
    const int numTiles = (V_N + 63) / 64;   // 782

    for (int tile = blockIdx.x; tile < numTiles; tile += gridDim.x) {
        const int n0 = tile * 64;
        __syncthreads();
        for (int i = tid; i < 64 * 32; i += 256) {
            int r = i >> 5, j = i & 31;
            int node = n0 + r;
            float4 v = (node < V_N) ? h4[(size_t)node * 32 + j]
                                    : make_float4(0.f, 0.f, 0.f, 0.f);
            uint2 u; u.x = pack2(v.x, v.y); u.y = pack2(v.z, v.w);
            *(uint2*)(sm + PQ_H + r * WPITCH + j * 8) = u;
        }
        __syncthreads();

        float d[2][8][4];
#pragma unroll
        for (int mi = 0; mi < 2; mi++)
#pragma unroll
            for (int ni = 0; ni < 8; ni++)
#pragma unroll
                for (int x = 0; x < 4; x++) d[mi][ni][x] = 0.f;

#pragma unroll
        for (int ks = 0; ks < 8; ks++) {
            uint32_t a[2][4], b[8][2];
#pragma unroll
            for (int mi = 0; mi < 2; mi++) {
                uint32_t addr = sH + (uint32_t)((wr * 32 + mi * 16 + l15) * WPITCH +
                                                (ks * 16 + kh) * 2);
                ldsm_x4(a[mi], addr);
            }
#pragma unroll
            for (int nj = 0; nj < 4; nj++) {
                uint32_t addr = sW + (uint32_t)((ks * 16 + l15) * BPITCH +
                                                (wc * 64 + nj * 16 + kh) * 2);
                uint32_t t[4];
                ldsm_x4_t(t, addr);
                b[2 * nj][0] = t[0]; b[2 * nj][1] = t[1];
                b[2 * nj + 1][0] = t[2]; b[2 * nj + 1][1] = t[3];
            }
#pragma unroll
            for (int mi = 0; mi < 2; mi++)
#pragma unroll
                for (int ni = 0; ni < 8; ni++)
                    mma_bf16(d[mi][ni], a[mi], b[ni]);
        }

#pragma unroll
        for (int mi = 0; mi < 2; mi++) {
            const int rA = wr * 32 + mi * 16 + g;
            const int nodeA = n0 + rA, nodeB = nodeA + 8;
#pragma unroll
            for (int ni = 0; ni < 8; ni++) {
                const int c = wc * 64 + ni * 8 + 2 * q;
                if (nodeA < V_N)
                    *(uint32_t*)&g_PQ[(size_t)nodeA * 256 + c] =
                        pack2(d[mi][ni][0], d[mi][ni][1]);
                if (nodeB < V_N)
                    *(uint32_t*)&g_PQ[(size_t)nodeB * 256 + c] =
                        pack2(d[mi][ni][2], d[mi][ni][3]);
            }
        }
    }
}

// ---------------------------------------------------------------------------
// k_r: R = h @ Wn1_top in 3-term split-bf16 (near-fp32 accuracy).
// ---------------------------------------------------------------------------
#define R_WH 0
#define R_WL 34816
#define R_HH 69632
#define R_HL 87040
#define SM_R_TOTAL 104448

__global__ __launch_bounds__(256, 2) void k_r(
    const float* __restrict__ h, const float* __restrict__ Wn1)
{
    extern __shared__ __align__(16) char sm[];
    const uint32_t sbase = smem_u32(sm);
    const int tid = threadIdx.x, wid = tid >> 5, lane = tid & 31;
    const int wr = wid & 1, wc = wid >> 1;
    const int g = lane >> 2, q = lane & 3;

    for (int i = tid; i < 128 * 128; i += 256) {
        int k = i >> 7, n = i & 127;
        float w = Wn1[k * 128 + n];
        __nv_bfloat16 whi = __float2bfloat16(w);
        float wlo = w - __bfloat162float(whi);
        *(__nv_bfloat16*)(sm + R_WH + k * WPITCH + n * 2) = whi;
        *(__nv_bfloat16*)(sm + R_WL + k * WPITCH + n * 2) = __float2bfloat16(wlo);
    }
    __syncthreads();

    const float4* h4 = (const float4*)h;
    const int numTiles = (V_N + 63) / 64;

    for (int tile = blockIdx.x; tile < numTiles; tile += gridDim.x) {
        const int n0 = tile * 64;
        __syncthreads();
        for (int i = tid; i < 64 * 32; i += 256) {
            int r = i >> 5, j = i & 31;
            int node = n0 + r;
            float4 v = (node < V_N) ? h4[(size_t)node * 32 + j]
                                    : make_float4(0.f, 0.f, 0.f, 0.f);
            __nv_bfloat16 h0 = __float2bfloat16(v.x), h1 = __float2bfloat16(v.y);
            __nv_bfloat16 h2 = __float2bfloat16(v.z), h3 = __float2bfloat16(v.w);
            uint2 uh, ul;
            uh.x = pack2(__bfloat162float(h0), __bfloat162float(h1));
            uh.y = pack2(__bfloat162float(h2), __bfloat162float(h3));
            ul.x = pack2(v.x - __bfloat162float(h0), v.y - __bfloat162float(h1));
            ul.y = pack2(v.z - __bfloat162float(h2), v.w - __bfloat162float(h3));
            *(uint2*)(sm + R_HH + r * WPITCH + j * 8) = uh;
            *(uint2*)(sm + R_HL + r * WPITCH + j * 8) = ul;
        }
        __syncthreads();

        float d[2][4][4];
        zero_d(d);
        gemm_tile<8, WPITCH, 0>(sbase + R_HH, sbase + R_WH, wr, wc, lane, d);
        gemm_tile<8, WPITCH, 0>(sbase + R_HH, sbase + R_WL, wr, wc, lane, d);
        gemm_tile<8, WPITCH, 0>(sbase + R_HL, sbase + R_WH, wr, wc, lane, d);

#pragma unroll
        for (int mi = 0; mi < 2; mi++) {
            const int rA = wr * 32 + mi * 16 + g;
            const int nodeA = n0 + rA, nodeB = nodeA + 8;
#pragma unroll
            for (int ni = 0; ni < 4; ni++) {
                const int c = wc * 32 + ni * 8 + 2 * q;
                if (nodeA < V_N)
                    *(float2*)&g_R[(size_t)nodeA * 128 + c] =
                        make_float2(d[mi][ni][0], d[mi][ni][1]);
                if (nodeB < V_N)
                    *(float2*)&g_R[(size_t)nodeB * 128 + c] =
                        make_float2(d[mi][ni][2], d[mi][ni][3]);
            }
        }
    }
}

// ---------------------------------------------------------------------------
// k_edge: 128-edge tiles, 512 threads, 1 sync/tile.
//   A2 = relu(P[src]+Q[dst]+b1);  S[dst] += relu(A2@W2+b2)  (fp16 red)
// GEMM3 folded into k_node via W3n.
// ---------------------------------------------------------------------------
#define SM_B1BF 0        // 128 bf16 = 256B
#define SM_B2S  256      // 128 f32 = 512B
#define SM_W2   768      // 128 x 272 = 34816
#define SM_A2A  35584
#define SM_A2B  70400
#define SM_EDGE_TOTAL 105216

__global__ __launch_bounds__(512, 1) void k_edge(
    const int* __restrict__ ei,
    const float* __restrict__ b1,
    const float* __restrict__ W2, const float* __restrict__ b2)
{
    extern __shared__ __align__(16) char sm[];
    float* b2s = (float*)(sm + SM_B2S);
    const uint32_t sbase = smem_u32(sm);
    const uint32_t sW2 = sbase + SM_W2;

    const int tid = threadIdx.x, wid = tid >> 5, lane = tid & 31;
    const int wr = wid & 3, wc = wid >> 2;
    const int g = lane >> 2, q = lane & 3;

    for (int i = tid; i < 128 * 128; i += 512) {
        int k = i >> 7, n = i & 127;
        *(__nv_bfloat16*)(sm + SM_W2 + k * WPITCH + n * 2) = __float2bfloat16(W2[i]);
    }
    if (tid < 128) {
        b2s[tid] = b2[tid];
        *(__nv_bfloat16*)(sm + SM_B1BF + tid * 2) = __float2bfloat16(b1[tid]);
    }
    __syncthreads();

    const int jg = tid & 15;                  // 8-col (16B) group
    const int r0 = tid >> 4;                  // base row (0..31)
    const uint4 Bv = *(const uint4*)(sm + SM_B1BF + jg * 16);

    const int numTiles = E_N / 128;   // 6250
    float d[2][4][4];
    int buf = 0;

    // Prologue: gather first tile into buffer A
    int tile = blockIdx.x;
    if (tile < numTiles) {
        const int e0 = tile * 128;
        char* a2p = sm + SM_A2A;
#pragma unroll
        for (int k = 0; k < 4; k++) {
            int r = r0 + 32 * k;
            int s = ei[e0 + r], t = ei[E_N + e0 + r];
            uint4 P = *(const uint4*)&g_PQ[(size_t)s * 256 + jg * 8];
            uint4 Q = *(const uint4*)&g_PQ[(size_t)t * 256 + 128 + jg * 8];
            uint4 o;
            o.x = addrelu2(P.x, Q.x, Bv.x);
            o.y = addrelu2(P.y, Q.y, Bv.y);
            o.z = addrelu2(P.z, Q.z, Bv.z);
            o.w = addrelu2(P.w, Q.w, Bv.w);
            *(uint4*)(a2p + r * WPITCH + jg * 16) = o;
        }
    }

    for (; tile < numTiles; tile += gridDim.x) {
        const int e0 = tile * 128;
        __syncthreads();   // A2[buf] ready; other buffer free

        // ---- GEMM2 on A2[buf] ----
        zero_d(d);
        gemm_tile<8, WPITCH, 0>(sbase + (buf ? SM_A2B : SM_A2A), sW2, wr, wc, lane, d);

        // ---- scatter S[dst] += relu(d + b2) as fp16 (direct from fragments) ----
        {
            const int rA = wr * 32 + g;
#pragma unroll
            for (int mi = 0; mi < 2; mi++) {
                const int rr = rA + mi * 16;
                const int d0 = ei[E_N + e0 + rr], d1 = ei[E_N + e0 + rr + 8];
#pragma unroll
                for (int ni = 0; ni < 4; ni++) {
                    const int c = wc * 32 + ni * 8 + 2 * q;
                    float2 bb = *(const float2*)&b2s[c];
                    __half2 v0 = __floats2half2_rn(
                        fmaxf(d[mi][ni][0] + bb.x, 0.f),
                        fmaxf(d[mi][ni][1] + bb.y, 0.f));
                    __half2 v1 = __floats2half2_rn(
                        fmaxf(d[mi][ni][2] + bb.x, 0.f),
                        fmaxf(d[mi][ni][3] + bb.y, 0.f));
                    red_add_h2(&g_S[(size_t)d0 * 128 + c], *(uint32_t*)&v0);
                    red_add_h2(&g_S[(size_t)d1 * 128 + c], *(uint32_t*)&v1);
                }
            }
        }

        // ---- gather next tile into the other buffer ----
        const int nt = tile + gridDim.x;
        if (nt < numTiles) {
            const int ne0 = nt * 128;
            char* a2p = sm + (buf ? SM_A2A : SM_A2B);
#pragma unroll
            for (int k = 0; k < 4; k++) {
                int r = r0 + 32 * k;
                int s = ei[ne0 + r], t = ei[E_N + ne0 + r];
                uint4 P = *(const uint4*)&g_PQ[(size_t)s * 256 + jg * 8];
                uint4 Q = *(const uint4*)&g_PQ[(size_t)t * 256 + 128 + jg * 8];
                uint4 o;
                o.x = addrelu2(P.x, Q.x, Bv.x);
                o.y = addrelu2(P.y, Q.y, Bv.y);
                o.z = addrelu2(P.z, Q.z, Bv.z);
                o.w = addrelu2(P.w, Q.w, Bv.w);
                *(uint4*)(a2p + r * WPITCH + jg * 16) = o;
            }
        }
        buf ^= 1;
    }
}

// ---------------------------------------------------------------------------
// k_node: T = relu(R + S@W3n + deg*bn3 + bn1); out = T@Wn2 (3-term split).
// 128-node tiles, 512 threads (4x4 warp grid).
// ---------------------------------------------------------------------------
#define N_B1  0         // bn1 512B
#define N_B2  512       // bn2 512B
#define N_B3  1024      // bn3 512B
#define N_W3N 1536      // fp16 W3n, 128 x 272 = 34816
#define N_W2H 36352
#define N_W2L 71168
#define N_XS  105984    // S staged fp16, 128 x 272
#define N_THI 140800
#define N_TLO 175616
#define SM_NODE_TOTAL 210432

__global__ __launch_bounds__(512, 1) void k_node(
    const float* __restrict__ bn1,
    const float* __restrict__ Wn2, const float* __restrict__ bn2,
    float* __restrict__ out)
{
    extern __shared__ __align__(16) char sm[];
    float* bn1s = (float*)(sm + N_B1);
    float* bn2s = (float*)(sm + N_B2);
    float* bn3s = (float*)(sm + N_B3);
    const uint32_t sbase = smem_u32(sm);
    const int tid = threadIdx.x, wid = tid >> 5, lane = tid & 31;
    const int wr = wid & 3, wc = wid >> 2;
    const int g = lane >> 2, q = lane & 3;

    for (int i = tid; i < 128 * 128; i += 512) {
        int k = i >> 7, n = i & 127;
        *(__half*)(sm + N_W3N + k * WPITCH + n * 2) = g_W3n[i];
        float w2 = Wn2[i];
        __nv_bfloat16 whi = __float2bfloat16(w2);
        *(__nv_bfloat16*)(sm + N_W2H + k * WPITCH + n * 2) = whi;
        *(__nv_bfloat16*)(sm + N_W2L + k * WPITCH + n * 2) =
            __float2bfloat16(w2 - __bfloat162float(whi));
    }
    if (tid < 128) { bn1s[tid] = bn1[tid]; bn2s[tid] = bn2[tid]; bn3s[tid] = g_bn3[tid]; }
    __syncthreads();

    float d[2][4][4];
    const int numTiles = (V_N + 127) / 128;   // 391

    for (int tile = blockIdx.x; tile < numTiles; tile += gridDim.x) {
        const int n0 = tile * 128;
        __syncthreads();
        // stage S (fp16 passthrough)
        for (int i = tid; i < 128 * 16; i += 512) {
            int r = i >> 4, j = i & 15;
            int node = n0 + r;
            uint4 v = (node < V_N) ? *(const uint4*)&g_S[(size_t)node * 128 + j * 8]
                                   : make_uint4(0, 0, 0, 0);
            *(uint4*)(sm + N_XS + r * WPITCH + j * 16) = v;
        }
        __syncthreads();

        // GEMM A: S @ W3n (fp16)
        zero_d(d);
        gemm_tile<8, WPITCH, 1>(sbase + N_XS, sbase + N_W3N, wr, wc, lane, d);

        // T = relu(d + R + deg*bn3 + bn1), split -> Thi/Tlo
#pragma unroll
        for (int mi = 0; mi < 2; mi++) {
            const int rA = wr * 32 + mi * 16 + g;
            const int nodeA = n0 + rA, nodeB = nodeA + 8;
            const float degA = (nodeA < V_N) ? (float)g_deg[nodeA] : 0.f;
            const float degB = (nodeB < V_N) ? (float)g_deg[nodeB] : 0.f;
#pragma unroll
            for (int ni = 0; ni < 4; ni++) {
                const int c = wc * 32 + ni * 8 + 2 * q;
                float2 bb = *(const float2*)&bn1s[c];
                float2 b3v = *(const float2*)&bn3s[c];
                float2 r0 = (nodeA < V_N) ? *(const float2*)&g_R[(size_t)nodeA * 128 + c]
                                          : make_float2(0.f, 0.f);
                float2 r1 = (nodeB < V_N) ? *(const float2*)&g_R[(size_t)nodeB * 128 + c]
                                          : make_float2(0.f, 0.f);
                float t0 = fmaxf(d[mi][ni][0] + r0.x + degA * b3v.x + bb.x, 0.f);
                float t1 = fmaxf(d[mi][ni][1] + r0.y + degA * b3v.y + bb.y, 0.f);
                float t2 = fmaxf(d[mi][ni][2] + r1.x + degB * b3v.x + bb.x, 0.f);
                float t3 = fmaxf(d[mi][ni][3] + r1.y + degB * b3v.y + bb.y, 0.f);
                __nv_bfloat16 h0 = __float2bfloat16(t0), h1 = __float2bfloat16(t1);
                __nv_bfloat16 h2 = __float2bfloat16(t2), h3 = __float2bfloat16(t3);
                *(uint32_t*)(sm + N_THI + rA * WPITCH + c * 2) =
                    pack2(__bfloat162float(h0), __bfloat162float(h1));
                *(uint32_t*)(sm + N_THI + (rA + 8) * WPITCH + c * 2) =
                    pack2(__bfloat162float(h2), __bfloat162float(h3));
                *(uint32_t*)(sm + N_TLO + rA * WPITCH + c * 2) =
                    pack2(t0 - __bfloat162float(h0), t1 - __bfloat162float(h1));
                *(uint32_t*)(sm + N_TLO + (rA + 8) * WPITCH + c * 2) =
                    pack2(t2 - __bfloat162float(h2), t3 - __bfloat162float(h3));
            }
        }
        __syncthreads();

        // GEMM B: out = Thi@W2hi + Thi@W2lo + Tlo@W2hi + bn2
        zero_d(d);
        gemm_tile<8, WPITCH, 0>(sbase + N_THI, sbase + N_W2H, wr, wc, lane, d);
        gemm_tile<8, WPITCH, 0>(sbase + N_THI, sbase + N_W2L, wr, wc, lane, d);
        gemm_tile<8, WPITCH, 0>(sbase + N_TLO, sbase + N_W2H, wr, wc, lane, d);

#pragma unroll
        for (int mi = 0; mi < 2; mi++) {
            const int rA = wr * 32 + mi * 16 + g;
            const int nodeA = n0 + rA, nodeB = nodeA + 8;
#pragma unroll
            for (int ni = 0; ni < 4; ni++) {
                const int c = wc * 32 + ni * 8 + 2 * q;
                float2 bb = *(const float2*)&bn2s[c];
                if (nodeA < V_N)
                    *(float2*)&out[(size_t)nodeA * 128 + c] =
                        make_float2(d[mi][ni][0] + bb.x, d[mi][ni][1] + bb.y);
                if (nodeB < V_N)
                    *(float2*)&out[(size_t)nodeB * 128 + c] =
                        make_float2(d[mi][ni][2] + bb.x, d[mi][ni][3] + bb.y);
            }
        }
    }
}

// ---------------------------------------------------------------------------
extern "C" void kernel_launch(void* const* d_in, const int* in_sizes, int n_in,
                              void* d_out, int out_size) {
    const float* h   = (const float*)d_in[0];
    const int*   ei  = (const int*)d_in[1];   // int32 (JAX x64 disabled)
    const float* W1  = (const float*)d_in[2];
    const float* b1  = (const float*)d_in[3];
    const float* W2  = (const float*)d_in[4];
    const float* b2  = (const float*)d_in[5];
    const float* W3  = (const float*)d_in[6];
    const float* b3  = (const float*)d_in[7];
    const float* Wn1 = (const float*)d_in[8];
    const float* bn1 = (const float*)d_in[9];
    const float* Wn2 = (const float*)d_in[10];
    const float* bn2 = (const float*)d_in[11];
    float*       out = (float*)d_out;

    cudaFuncSetAttribute(k_pq,   cudaFuncAttributeMaxDynamicSharedMemorySize, SM_PQ_TOTAL);
    cudaFuncSetAttribute(k_r,    cudaFuncAttributeMaxDynamicSharedMemorySize, SM_R_TOTAL);
    cudaFuncSetAttribute(k_edge, cudaFuncAttributeMaxDynamicSharedMemorySize, SM_EDGE_TOTAL);
    cudaFuncSetAttribute(k_node, cudaFuncAttributeMaxDynamicSharedMemorySize, SM_NODE_TOTAL);

    k_zero<<<512, 256>>>();
    k_deg<<<1024, 256>>>(ei);
    k_w3n<<<128, 128>>>(W3, b3, Wn1);
    k_pq<<<296, 256, SM_PQ_TOTAL>>>(h, W1);
    k_r<<<296, 256, SM_R_TOTAL>>>(h, Wn1);
    k_edge<<<148, 512, SM_EDGE_TOTAL>>>(ei, b1, W2, b2);
    k_node<<<148, 512, SM_NODE_TOTAL>>>(bn1, Wn2, bn2, out);
}